// round 9
// baseline (speedup 1.0000x reference)
#include <cuda_runtime.h>
#include <cuda_fp16.h>
#include <mma.h>
#include <math.h>
#include <stdint.h>

using namespace nvcuda;

// ---------------- problem constants ----------------
#define S_      2048
#define HID_    2048
#define H_      16
#define D_NOPE  128
#define D_ROPE  64
#define D_V     128
#define QHEAD   192
#define QL_     1536
#define KVL_    512
#define CKV_W   576
#define KVA_PAD 768
#define QDIM    3072
#define KVDIM   4096
#define EPS_    1e-6f
#define SCALE_  0.07216878364870322f

// ---------------- scratch ----------------
__device__ __half g_x     [S_ * HID_];
__device__ __half g_wqa   [HID_ * QL_];
__device__ __half g_wqb   [QL_ * QDIM];
__device__ __half g_wkva  [HID_ * KVA_PAD];
__device__ __half g_wkvb  [KVL_ * KVDIM];
__device__ __half g_wo    [H_ * D_V * HID_];
__device__ float  g_qa    [S_ * QL_];
__device__ __half g_qn    [S_ * QL_];
__device__ float  g_ckv   [S_ * CKV_W];
__device__ __half g_cnorm [S_ * KVL_];
__device__ float  g_kpe   [S_ * D_ROPE];
__device__ float  g_q     [S_ * QDIM];
__device__ float  g_kv    [S_ * KVDIM];
__device__ __half g_Q     [H_ * S_ * QHEAD];
__device__ __half g_K     [H_ * S_ * QHEAD];
__device__ __half g_V     [H_ * D_V * S_];
__device__ __half g_attn  [S_ * (H_ * D_V)];

__device__ __forceinline__ int perm16(int c) {
    int j = c & 15;
    return (c & ~15) | (((j >> 1) & 3) << 2) | ((j >> 3) << 1) | (j & 1);
}
__device__ __forceinline__ uint32_t smem_u32(const void* p) {
    uint32_t a;
    asm("{ .reg .u64 t; cvta.to.shared.u64 t, %1; cvt.u32.u64 %0, t; }" : "=r"(a) : "l"(p));
    return a;
}
__device__ __forceinline__ void cp16(uint32_t d, const void* s) {
    asm volatile("cp.async.ca.shared.global [%0], [%1], 16;" :: "r"(d), "l"(s));
}
__device__ __forceinline__ void cp_commit() {
    asm volatile("cp.async.commit_group;" ::: "memory");
}
template<int N> __device__ __forceinline__ void cp_wait() {
    asm volatile("cp.async.wait_group %0;" :: "n"(N) : "memory");
}
__device__ __forceinline__ void mma16(float* c, uint32_t a0, uint32_t a1, uint32_t a2, uint32_t a3,
                                      uint32_t b0, uint32_t b1) {
    asm volatile(
        "mma.sync.aligned.m16n8k16.row.col.f32.f16.f16.f32 "
        "{%0,%1,%2,%3}, {%4,%5,%6,%7}, {%8,%9}, {%0,%1,%2,%3};"
        : "+f"(c[0]), "+f"(c[1]), "+f"(c[2]), "+f"(c[3])
        : "r"(a0), "r"(a1), "r"(a2), "r"(a3), "r"(b0), "r"(b1));
}

// ---------------- prep: fused fp16 conversion (5 tensors + padded kv_a, 1 launch) ----------------
__global__ void conv_multi_kernel(
    const float4* __restrict__ s0, __half2* __restrict__ d0, int n0,
    const float4* __restrict__ s1, __half2* __restrict__ d1, int n1,
    const float4* __restrict__ s2, __half2* __restrict__ d2, int n2,
    const float4* __restrict__ s3, __half2* __restrict__ d3, int n3,
    const float4* __restrict__ s4, __half2* __restrict__ d4, int n4,
    const float* __restrict__ kva, __half* __restrict__ wkva, int n5)
{
    int i = blockIdx.x * blockDim.x + threadIdx.x;
    int j = i;
    if (j < n0) {
        float4 v = s0[j];
        d0[2*j+0] = __floats2half2_rn(v.x, v.y); d0[2*j+1] = __floats2half2_rn(v.z, v.w);
        return;
    }
    j -= n0;
    if (j < n1) {
        float4 v = s1[j];
        d1[2*j+0] = __floats2half2_rn(v.x, v.y); d1[2*j+1] = __floats2half2_rn(v.z, v.w);
        return;
    }
    j -= n1;
    if (j < n2) {
        float4 v = s2[j];
        d2[2*j+0] = __floats2half2_rn(v.x, v.y); d2[2*j+1] = __floats2half2_rn(v.z, v.w);
        return;
    }
    j -= n2;
    if (j < n3) {
        float4 v = s3[j];
        d3[2*j+0] = __floats2half2_rn(v.x, v.y); d3[2*j+1] = __floats2half2_rn(v.z, v.w);
        return;
    }
    j -= n3;
    if (j < n4) {
        float4 v = s4[j];
        d4[2*j+0] = __floats2half2_rn(v.x, v.y); d4[2*j+1] = __floats2half2_rn(v.z, v.w);
        return;
    }
    j -= n4;
    if (j < n5) {
        int k = (4 * j) / KVA_PAD, n = (4 * j) % KVA_PAD;
        __half2 lo, hi;
        if (n < CKV_W) {
            float4 v = *reinterpret_cast<const float4*>(kva + (size_t)k * CKV_W + n);
            lo = __floats2half2_rn(v.x, v.y); hi = __floats2half2_rn(v.z, v.w);
        } else {
            lo = __floats2half2_rn(0.f, 0.f); hi = lo;
        }
        __half2* dp = reinterpret_cast<__half2*>(wkva + (size_t)k * KVA_PAD + n);
        dp[0] = lo; dp[1] = hi;
    }
}

// ---------------- pipelined fp16 GEMM, dual problem sets ----------------
// BM=128, BN=128, BK=64, 256 threads, 3-stage cp.async, 2 CTAs/SM
#define A_STRH 72     // halfs
#define B_STRH 136    // halfs: 128 + 8 pad
#define A_SBYT (128 * A_STRH * 2)   // 18432
#define B_SBYT (64 * B_STRH * 2)    // 17408
#define STG_P  (A_SBYT + B_SBYT)    // 35840
#define SMEM_P (3 * STG_P)          // 107520

__global__ __launch_bounds__(256, 2)
void pgemm_kernel(const __half* __restrict__ A, int lda, int K,
                  const __half* __restrict__ B, int ldb,
                  float* __restrict__ C, int ldc, int N, int nt1,
                  const __half* __restrict__ A2, int lda2, int K2,
                  const __half* __restrict__ B2, int ldb2,
                  float* __restrict__ C2, int ldc2, int N2)
{
    int bx = blockIdx.x;
    if (bx >= nt1) {
        A = A2; lda = lda2; K = K2; B = B2; ldb = ldb2; C = C2; ldc = ldc2; N = N2;
        bx -= nt1;
    }
    const int row0 = blockIdx.y * 128;
    const int col0 = bx * 128;
    const int nk = K / 64;

    extern __shared__ char smem[];
    const uint32_t sb = smem_u32(smem);
    const int tid = threadIdx.x;
    const int wid = tid >> 5;
    const int wm  = wid >> 2;     // 0..1 -> rows wm*64
    const int wn  = wid & 3;      // 0..3 -> cols wn*32

    auto issue = [&](int t) {
        const int s = t % 3;
        const int k0 = t * 64;
        uint32_t ab = sb + s * STG_P;
        #pragma unroll
        for (int i = 0; i < 4; i++) {
            int idx = i * 256 + tid;
            int r = idx >> 3, c = idx & 7;
            cp16(ab + r * (A_STRH * 2) + c * 16, A + (size_t)(row0 + r) * lda + k0 + c * 8);
        }
        uint32_t bb = sb + s * STG_P + A_SBYT;
        #pragma unroll
        for (int i = 0; i < 4; i++) {
            int idx = i * 256 + tid;
            int kr = idx >> 4, c = idx & 15;
            cp16(bb + kr * (B_STRH * 2) + c * 16, B + (size_t)(k0 + kr) * ldb + col0 + c * 8);
        }
    };

    typedef wmma::fragment<wmma::matrix_a, 16, 16, 16, __half, wmma::row_major> AFrag;
    typedef wmma::fragment<wmma::matrix_b, 16, 16, 16, __half, wmma::row_major> BFrag;
    wmma::fragment<wmma::accumulator, 16, 16, 16, float> acc[4][2];
    #pragma unroll
    for (int i = 0; i < 4; i++)
        #pragma unroll
        for (int j = 0; j < 2; j++) wmma::fill_fragment(acc[i][j], 0.0f);

    issue(0); cp_commit();
    if (nk > 1) { issue(1); cp_commit(); }

    for (int t = 0; t < nk; t++) {
        if (t + 1 < nk) cp_wait<1>(); else cp_wait<0>();
        __syncthreads();
        if (t + 2 < nk) { issue(t + 2); cp_commit(); }

        const __half* As = reinterpret_cast<const __half*>(smem + (t % 3) * STG_P);
        const __half* Bs = reinterpret_cast<const __half*>(smem + (t % 3) * STG_P + A_SBYT);

        #pragma unroll
        for (int kk = 0; kk < 4; kk++) {
            AFrag af[4];
            BFrag bf[2];
            #pragma unroll
            for (int mf = 0; mf < 4; mf++)
                wmma::load_matrix_sync(af[mf], As + (wm * 64 + mf * 16) * A_STRH + kk * 16, A_STRH);
            #pragma unroll
            for (int nf = 0; nf < 2; nf++)
                wmma::load_matrix_sync(bf[nf], Bs + (kk * 16) * B_STRH + wn * 32 + nf * 16, B_STRH);
            #pragma unroll
            for (int mf = 0; mf < 4; mf++)
                #pragma unroll
                for (int nf = 0; nf < 2; nf++)
                    wmma::mma_sync(acc[mf][nf], af[mf], bf[nf], acc[mf][nf]);
        }
        __syncthreads();
    }

    #pragma unroll
    for (int mf = 0; mf < 4; mf++) {
        int gr = row0 + wm * 64 + mf * 16;
        #pragma unroll
        for (int nf = 0; nf < 2; nf++) {
            int gc = col0 + wn * 32 + nf * 16;
            if (gc + 16 <= N)
                wmma::store_matrix_sync(C + (size_t)gr * ldc + gc, acc[mf][nf], ldc,
                                        wmma::mem_row_major);
        }
    }
}

// ---------------- fused RMSNorm: grid.y 0 -> q_a, 1 -> ckv ----------------
__global__ __launch_bounds__(256)
void rms_fused_kernel(const float* __restrict__ qa, const float* __restrict__ wq,
                      const float* __restrict__ ckv, const float* __restrict__ wkv,
                      const float* __restrict__ cosT, const float* __restrict__ sinT,
                      const int* __restrict__ pos,
                      __half* __restrict__ qn, __half* __restrict__ cnorm,
                      float* __restrict__ kpe, float* __restrict__ cache)
{
    const int s = blockIdx.x;
    const int tid = threadIdx.x;
    __shared__ float sred[256];

    if (blockIdx.y == 0) {
        const float* x = qa + (size_t)s * QL_;
        __half*      y = qn + (size_t)s * QL_;
        float v[6];
        float local = 0.f;
        #pragma unroll
        for (int i = 0; i < 6; i++) { int c = tid + i * 256; v[i] = x[c]; local += v[i] * v[i]; }
        sred[tid] = local; __syncthreads();
        for (int st = 128; st > 0; st >>= 1) {
            if (tid < st) sred[tid] += sred[tid + st];
            __syncthreads();
        }
        float scale = rsqrtf(sred[0] / (float)QL_ + EPS_);
        #pragma unroll
        for (int i = 0; i < 6; i++) { int c = tid + i * 256; y[c] = __float2half(v[i] * scale * wq[c]); }
    } else {
        const float* x = ckv + (size_t)s * CKV_W;
        float v[2];
        float local = 0.f;
        #pragma unroll
        for (int i = 0; i < 2; i++) { int c = tid + i * 256; v[i] = x[c]; local += v[i] * v[i]; }
        sred[tid] = local; __syncthreads();
        for (int st = 128; st > 0; st >>= 1) {
            if (tid < st) sred[tid] += sred[tid + st];
            __syncthreads();
        }
        float scale = rsqrtf(sred[0] / (float)KVL_ + EPS_);
        #pragma unroll
        for (int i = 0; i < 2; i++) {
            int c = tid + i * 256;
            float y = v[i] * scale * wkv[c];
            cnorm[(size_t)s * KVL_ + c] = __float2half(y);
            cache[(size_t)s * CKV_W + c] = y;
        }
        if (tid < D_ROPE) {
            int p = pos[s];
            const float* cr = cosT + (size_t)p * D_ROPE;
            const float* sr = sinT + (size_t)p * D_ROPE;
            const float* t  = x + KVL_;
            int i = tid;
            float val;
            if (i < 32) val = t[2 * i] * cr[i] - t[2 * i + 1] * sr[i];
            else { int i2 = i - 32; val = t[2 * i2 + 1] * cr[i] + t[2 * i2] * sr[i]; }
            kpe[(size_t)s * D_ROPE + i] = val;
            cache[(size_t)s * CKV_W + KVL_ + i] = val;
        }
    }
}

// ---------------- fused assemble Q/K (perm16) + V transpose ----------------
__global__ __launch_bounds__(256)
void assemble_fused_kernel(const float* __restrict__ q, const float* __restrict__ kv,
                           const float* __restrict__ kpe,
                           const float* __restrict__ cosT, const float* __restrict__ sinT,
                           const int* __restrict__ pos,
                           __half* __restrict__ Q, __half* __restrict__ K,
                           __half* __restrict__ V)
{
    const int s0 = blockIdx.x * 64;
    const int h  = blockIdx.y;
    const int tid = threadIdx.x;

    #pragma unroll
    for (int it = 0; it < 48; it++) {
        int idx = it * 256 + tid;
        int sl = idx / QHEAD, d = idx % QHEAD;
        int s = s0 + sl;
        const float* qrow  = q  + (size_t)s * QDIM  + h * QHEAD;
        const float* kvrow = kv + (size_t)s * KVDIM + h * (D_NOPE + D_V);
        const size_t off = ((size_t)h * S_ + s) * QHEAD;

        float qv;
        if (d < D_NOPE) qv = qrow[d];
        else {
            int p = pos[s];
            const float* cr = cosT + (size_t)p * D_ROPE;
            const float* sr = sinT + (size_t)p * D_ROPE;
            const float* t  = qrow + D_NOPE;
            int i = d - D_NOPE;
            if (i < 32) qv = t[2 * i] * cr[i] - t[2 * i + 1] * sr[i];
            else { int i2 = i - 32; qv = t[2 * i2 + 1] * cr[i] + t[2 * i2] * sr[i]; }
        }
        float kvv = (d < D_NOPE) ? kvrow[d] : kpe[(size_t)s * D_ROPE + (d - D_NOPE)];
        int pd = perm16(d);
        Q[off + pd] = __float2half(qv);
        K[off + pd] = __float2half(kvv);
    }

    __shared__ float vt[64 * 132];
    #pragma unroll
    for (int i = 0; i < 32; i++) {
        int idx = i * 256 + tid;
        int sl = idx >> 7, d = idx & 127;
        vt[sl * 132 + d] = kv[(size_t)(s0 + sl) * KVDIM + h * (D_NOPE + D_V) + D_NOPE + d];
    }
    __syncthreads();
    #pragma unroll
    for (int i = 0; i < 32; i++) {
        int idx = i * 256 + tid;
        int d = idx >> 6, sl = idx & 63;
        V[((size_t)h * D_V + d) * S_ + s0 + perm16(sl)] = __float2half(vt[sl * 132 + d]);
    }
}

// ---------------- fused flash attention (fp16) ----------------
#define QS_STR 200
#define KS_STR 200
#define VS_STR 40
#define SF_STR 36
#define PH_STR 40
#define QS_OFF 0
#define KS_OFF 25600
#define KS_BYTES 12800
#define VS_OFF (KS_OFF + 2*KS_BYTES)
#define VS_BYTES 10240
#define SF_OFF (VS_OFF + 2*VS_BYTES)
#define PH_OFF (SF_OFF + 64*SF_STR*4)
#define M_OFF  (PH_OFF + 64*PH_STR*2)
#define L_OFF  (M_OFF + 256)
#define AL_OFF (L_OFF + 256)
#define FLASH_SMEM (AL_OFF + 256)

__global__ __launch_bounds__(256, 2)
void flash_kernel(const __half* __restrict__ Q, const __half* __restrict__ K,
                  const __half* __restrict__ V, __half* __restrict__ attn)
{
    const int qt = blockIdx.x;
    const int h  = blockIdx.y;
    const int q0 = qt * 64;
    const int nt = 2 * qt + 2;

    extern __shared__ char sm[];
    const uint32_t sb = smem_u32(sm);
    float* mP = reinterpret_cast<float*>(sm + M_OFF);
    float* lP = reinterpret_cast<float*>(sm + L_OFF);
    float* aP = reinterpret_cast<float*>(sm + AL_OFF);

    const int tid = threadIdx.x;
    const int wid = tid >> 5;
    const int lid = tid & 31;
    const int gl  = lid >> 2;
    const int tg  = lid & 3;
    const int wm  = wid >> 2;
    const int wn  = wid & 3;

    const __half* Qg = Q + ((size_t)h * S_ + q0) * QHEAD;
    const __half* Kg = K + (size_t)h * S_ * QHEAD;
    const __half* Vg = V + (size_t)h * D_V * S_;

    auto issueKV = [&](int t, int st) {
        const __half* kp = Kg + (size_t)t * 32 * QHEAD;
        uint32_t kd = sb + KS_OFF + st * KS_BYTES;
        #pragma unroll
        for (int i = 0; i < 3; i++) {
            int idx = i * 256 + tid;
            int r = idx / 24, c = idx % 24;
            cp16(kd + r * (KS_STR * 2) + c * 16, kp + (size_t)r * QHEAD + c * 8);
        }
        uint32_t vd = sb + VS_OFF + st * VS_BYTES;
        #pragma unroll
        for (int i = 0; i < 2; i++) {
            int idx = i * 256 + tid;
            int d = idx >> 2, c = idx & 3;
            cp16(vd + d * (VS_STR * 2) + c * 16, Vg + (size_t)d * S_ + t * 32 + c * 8);
        }
    };

    #pragma unroll
    for (int i = 0; i < 6; i++) {
        int idx = i * 256 + tid;
        int r = idx / 24, c = idx % 24;
        cp16(sb + QS_OFF + r * (QS_STR * 2) + c * 16, Qg + (size_t)r * QHEAD + c * 8);
    }
    issueKV(0, 0);
    cp_commit();

    if (tid < 64) { mP[tid] = -1e30f; lP[tid] = 0.f; }

    float oacc[2][4][4];
    #pragma unroll
    for (int a = 0; a < 2; a++)
        #pragma unroll
        for (int b = 0; b < 4; b++)
            #pragma unroll
            for (int c = 0; c < 4; c++) oacc[a][b][c] = 0.f;

    const char* QsB = sm + QS_OFF;
    char* SfB = sm + SF_OFF;
    char* PhB = sm + PH_OFF;

    for (int t = 0; t < nt; t++) {
        const int st = t & 1;
        if (t + 1 < nt) { issueKV(t + 1, st ^ 1); cp_commit(); cp_wait<1>(); }
        else            { cp_wait<0>(); }
        __syncthreads();

        const char* KsB = sm + KS_OFF + st * KS_BYTES;
        float sacc[2][4] = {{0.f,0.f,0.f,0.f},{0.f,0.f,0.f,0.f}};
        const int bRow = wn * 8 + gl;
        #pragma unroll 4
        for (int kk = 0; kk < 12; kk++) {
            uint2 bb = *reinterpret_cast<const uint2*>(
                KsB + (bRow * KS_STR + kk * 16 + 4 * tg) * 2);
            #pragma unroll
            for (int mf = 0; mf < 2; mf++) {
                int r0 = wm * 32 + mf * 16 + gl;
                uint2 lo = *reinterpret_cast<const uint2*>(
                    QsB + (r0 * QS_STR + kk * 16 + 4 * tg) * 2);
                uint2 hi = *reinterpret_cast<const uint2*>(
                    QsB + ((r0 + 8) * QS_STR + kk * 16 + 4 * tg) * 2);
                mma16(sacc[mf], lo.x, hi.x, lo.y, hi.y, bb.x, bb.y);
            }
        }
        #pragma unroll
        for (int mf = 0; mf < 2; mf++) {
            int r0 = wm * 32 + mf * 16 + gl;
            int c0 = wn * 8 + 2 * tg;
            *reinterpret_cast<float2*>(SfB + (r0 * SF_STR + c0) * 4) =
                make_float2(sacc[mf][0], sacc[mf][1]);
            *reinterpret_cast<float2*>(SfB + ((r0 + 8) * SF_STR + c0) * 4) =
                make_float2(sacc[mf][2], sacc[mf][3]);
        }
        __syncthreads();

        {
            const int row = tid >> 2;
            const int cb  = (tid & 3) * 8;
            float* srow = reinterpret_cast<float*>(SfB) + row * SF_STR + cb;
            __half* prow = reinterpret_cast<__half*>(PhB) + row * PH_STR;
            float4 v0 = *reinterpret_cast<float4*>(srow);
            float4 v1 = *reinterpret_cast<float4*>(srow + 4);
            float v[8] = {v0.x, v0.y, v0.z, v0.w, v1.x, v1.y, v1.z, v1.w};
            const int rg = q0 + row;
            const int key0 = t * 32 + cb;
            const bool msk = (t >= 2 * qt);
            float mx = -1e30f;
            #pragma unroll
            for (int j = 0; j < 8; j++) {
                float val = v[j] * SCALE_;
                if (msk && (key0 + j) > rg) val = -1e30f;
                v[j] = val;
                mx = fmaxf(mx, val);
            }
            mx = fmaxf(mx, __shfl_xor_sync(0xffffffffu, mx, 1));
            mx = fmaxf(mx, __shfl_xor_sync(0xffffffffu, mx, 2));
            float mold = mP[row];
            float mnew = fmaxf(mold, mx);
            float al = __expf(mold - mnew);
            float sum = 0.f;
            #pragma unroll
            for (int j = 0; j < 8; j++) {
                float p = __expf(v[j] - mnew);
                sum += p;
                prow[perm16(cb + j)] = __float2half(p);
            }
            sum += __shfl_xor_sync(0xffffffffu, sum, 1);
            sum += __shfl_xor_sync(0xffffffffu, sum, 2);
            if ((tid & 3) == 0) {
                mP[row] = mnew;
                lP[row] = lP[row] * al + sum;
                aP[row] = al;
            }
        }
        __syncthreads();

        const char* VsB = sm + VS_OFF + st * VS_BYTES;
        #pragma unroll
        for (int mf = 0; mf < 2; mf++) {
            int r0 = wm * 32 + mf * 16 + gl;
            float a0 = aP[r0], a8 = aP[r0 + 8];
            #pragma unroll
            for (int nf = 0; nf < 4; nf++) {
                oacc[mf][nf][0] *= a0; oacc[mf][nf][1] *= a0;
                oacc[mf][nf][2] *= a8; oacc[mf][nf][3] *= a8;
            }
        }
        #pragma unroll
        for (int kk = 0; kk < 2; kk++) {
            uint2 alo[2], ahi[2];
            #pragma unroll
            for (int mf = 0; mf < 2; mf++) {
                int r0 = wm * 32 + mf * 16 + gl;
                alo[mf] = *reinterpret_cast<const uint2*>(
                    PhB + (r0 * PH_STR + kk * 16 + 4 * tg) * 2);
                ahi[mf] = *reinterpret_cast<const uint2*>(
                    PhB + ((r0 + 8) * PH_STR + kk * 16 + 4 * tg) * 2);
            }
            #pragma unroll
            for (int nf = 0; nf < 4; nf++) {
                int nc = wn * 32 + nf * 8 + gl;
                uint2 bv = *reinterpret_cast<const uint2*>(
                    VsB + (nc * VS_STR + kk * 16 + 4 * tg) * 2);
                #pragma unroll
                for (int mf = 0; mf < 2; mf++)
                    mma16(oacc[mf][nf], alo[mf].x, ahi[mf].x, alo[mf].y, ahi[mf].y, bv.x, bv.y);
            }
        }
        __syncthreads();
    }

    #pragma unroll
    for (int mf = 0; mf < 2; mf++) {
        int r0 = wm * 32 + mf * 16 + gl;
        float inv0 = 1.f / lP[r0];
        float inv8 = 1.f / lP[r0 + 8];
        #pragma unroll
        for (int nf = 0; nf < 4; nf++) {
            int col = h * D_V + wn * 32 + nf * 8 + 2 * tg;
            __half2* o0 = reinterpret_cast<__half2*>(attn + (size_t)(q0 + r0) * (H_ * D_V) + col);
            __half2* o8 = reinterpret_cast<__half2*>(attn + (size_t)(q0 + r0 + 8) * (H_ * D_V) + col);
            *o0 = __floats2half2_rn(oacc[mf][nf][0] * inv0, oacc[mf][nf][1] * inv0);
            *o8 = __floats2half2_rn(oacc[mf][nf][2] * inv8, oacc[mf][nf][3] * inv8);
        }
    }
}

// ---------------- host launch ----------------
extern "C" void kernel_launch(void* const* d_in, const int* in_sizes, int n_in,
                              void* d_out, int out_size)
{
    const float* x       = (const float*)d_in[0];
    const int*   pos     = (const int*)  d_in[2];
    const float* cosT    = (const float*)d_in[3];
    const float* sinT    = (const float*)d_in[4];
    const float* q_a_w   = (const float*)d_in[5];
    const float* q_a_ln  = (const float*)d_in[6];
    const float* q_b_w   = (const float*)d_in[7];
    const float* kv_a_w  = (const float*)d_in[8];
    const float* kv_a_ln = (const float*)d_in[9];
    const float* kv_b_w  = (const float*)d_in[10];
    const float* o_w     = (const float*)d_in[11];
    float* out = (float*)d_out;
    float* out_cache = out + (size_t)S_ * HID_;

    __half *xc, *wqa, *wqb, *wkva, *wkvb, *wo, *qn, *cnorm, *Q, *K, *V, *attn;
    float *qa, *ckv, *kpe, *q, *kv;
    cudaGetSymbolAddress((void**)&xc,     g_x);
    cudaGetSymbolAddress((void**)&wqa,    g_wqa);
    cudaGetSymbolAddress((void**)&wqb,    g_wqb);
    cudaGetSymbolAddress((void**)&wkva,   g_wkva);
    cudaGetSymbolAddress((void**)&wkvb,   g_wkvb);
    cudaGetSymbolAddress((void**)&wo,     g_wo);
    cudaGetSymbolAddress((void**)&qa,     g_qa);
    cudaGetSymbolAddress((void**)&qn,     g_qn);
    cudaGetSymbolAddress((void**)&ckv,    g_ckv);
    cudaGetSymbolAddress((void**)&cnorm,  g_cnorm);
    cudaGetSymbolAddress((void**)&kpe,    g_kpe);
    cudaGetSymbolAddress((void**)&q,      g_q);
    cudaGetSymbolAddress((void**)&kv,     g_kv);
    cudaGetSymbolAddress((void**)&Q,      g_Q);
    cudaGetSymbolAddress((void**)&K,      g_K);
    cudaGetSymbolAddress((void**)&V,      g_V);
    cudaGetSymbolAddress((void**)&attn,   g_attn);

    cudaFuncSetAttribute(pgemm_kernel, cudaFuncAttributeMaxDynamicSharedMemorySize, SMEM_P);
    cudaFuncSetAttribute(flash_kernel, cudaFuncAttributeMaxDynamicSharedMemorySize, FLASH_SMEM);

    // prep: all conversions in 1 launch
    {
        int n0 = S_ * HID_ / 4, n1 = HID_ * QL_ / 4, n2 = QL_ * QDIM / 4,
            n3 = KVL_ * KVDIM / 4, n4 = H_ * D_V * HID_ / 4,
            n5 = HID_ * KVA_PAD / 4;
        int total = n0 + n1 + n2 + n3 + n4 + n5;
        conv_multi_kernel<<<(total + 255) / 256, 256>>>(
            (const float4*)x,      (__half2*)xc,   n0,
            (const float4*)q_a_w,  (__half2*)wqa,  n1,
            (const float4*)q_b_w,  (__half2*)wqb,  n2,
            (const float4*)kv_b_w, (__half2*)wkvb, n3,
            (const float4*)o_w,    (__half2*)wo,   n4,
            kv_a_w, wkva, n5);
    }

    dim3 blk(256);

    // 1) fused: qa = x@q_a_w (12 tiles) ; ckv = x@kv_a_w (6 tiles, padded)
    pgemm_kernel<<<dim3(18, S_/128), blk, SMEM_P>>>(
        xc, HID_, HID_, wqa, QL_, qa, QL_, QL_, 12,
        xc, HID_, HID_, wkva, KVA_PAD, ckv, CKV_W, CKV_W);
    // 2) fused RMSNorms
    rms_fused_kernel<<<dim3(S_, 2), blk>>>(qa, q_a_ln, ckv, kv_a_ln, cosT, sinT, pos,
                                           qn, cnorm, kpe, out_cache);
    // 3) fused: q = qn@q_b_w (24 tiles, K=1536) ; kv = cnorm@kv_b_w (32 tiles, K=512)
    pgemm_kernel<<<dim3(56, S_/128), blk, SMEM_P>>>(
        qn, QL_, QL_, wqb, QDIM, q, QDIM, QDIM, 24,
        cnorm, KVL_, KVL_, wkvb, KVDIM, kv, KVDIM, KVDIM);
    // 4) fused assemble Q/K + V transpose
    assemble_fused_kernel<<<dim3(S_/64, H_), blk>>>(q, kv, kpe, cosT, sinT, pos, Q, K, V);
    // 5) fused flash attention
    flash_kernel<<<dim3(S_/64, H_), blk, FLASH_SMEM>>>(Q, K, V, attn);
    // 6) out = attn @ o_w
    pgemm_kernel<<<dim3(HID_/128, S_/128), blk, SMEM_P>>>(
        attn, H_*D_V, H_*D_V, wo, HID_, out, HID_, HID_, HID_/128,
        nullptr, 0, 0, nullptr, 0, nullptr, 0, 0);
}

// round 10
// speedup vs baseline: 1.0275x; 1.0275x over previous
#include <cuda_runtime.h>
#include <cuda_fp16.h>
#include <mma.h>
#include <math.h>
#include <stdint.h>

using namespace nvcuda;

// ---------------- problem constants ----------------
#define S_      2048
#define HID_    2048
#define H_      16
#define D_NOPE  128
#define D_ROPE  64
#define D_V     128
#define QHEAD   192
#define QL_     1536
#define KVL_    512
#define CKV_W   576
#define KVA_PAD 768
#define QDIM    3072
#define KVDIM   4096
#define EPS_    1e-6f
#define SCALE_  0.07216878364870322f

// ---------------- scratch ----------------
__device__ __half g_x     [S_ * HID_];
__device__ __half g_wqa   [HID_ * QL_];
__device__ __half g_wqb   [QL_ * QDIM];
__device__ __half g_wkva  [HID_ * KVA_PAD];
__device__ __half g_wkvb  [KVL_ * KVDIM];
__device__ __half g_wo    [H_ * D_V * HID_];
__device__ float  g_qa    [S_ * QL_];
__device__ __half g_qn    [S_ * QL_];
__device__ float  g_ckv   [S_ * CKV_W];
__device__ __half g_cnorm [S_ * KVL_];
__device__ float  g_kpe   [S_ * D_ROPE];
__device__ float  g_q     [S_ * QDIM];
__device__ float  g_kv    [S_ * KVDIM];
__device__ __half g_Q     [H_ * S_ * QHEAD];
__device__ __half g_K     [H_ * S_ * QHEAD];
__device__ __half g_V     [H_ * D_V * S_];
__device__ __half g_attn  [S_ * (H_ * D_V)];

__device__ __forceinline__ int perm16(int c) {
    int j = c & 15;
    return (c & ~15) | (((j >> 1) & 3) << 2) | ((j >> 3) << 1) | (j & 1);
}
__device__ __forceinline__ uint32_t smem_u32(const void* p) {
    uint32_t a;
    asm("{ .reg .u64 t; cvta.to.shared.u64 t, %1; cvt.u32.u64 %0, t; }" : "=r"(a) : "l"(p));
    return a;
}
__device__ __forceinline__ void cp16(uint32_t d, const void* s) {
    asm volatile("cp.async.ca.shared.global [%0], [%1], 16;" :: "r"(d), "l"(s));
}
__device__ __forceinline__ void cp_commit() {
    asm volatile("cp.async.commit_group;" ::: "memory");
}
template<int N> __device__ __forceinline__ void cp_wait() {
    asm volatile("cp.async.wait_group %0;" :: "n"(N) : "memory");
}
__device__ __forceinline__ void mma16(float* c, uint32_t a0, uint32_t a1, uint32_t a2, uint32_t a3,
                                      uint32_t b0, uint32_t b1) {
    asm volatile(
        "mma.sync.aligned.m16n8k16.row.col.f32.f16.f16.f32 "
        "{%0,%1,%2,%3}, {%4,%5,%6,%7}, {%8,%9}, {%0,%1,%2,%3};"
        : "+f"(c[0]), "+f"(c[1]), "+f"(c[2]), "+f"(c[3])
        : "r"(a0), "r"(a1), "r"(a2), "r"(a3), "r"(b0), "r"(b1));
}

// ---------------- prep: fused fp16 conversion (5 tensors + padded kv_a, 1 launch) ----------------
__global__ void conv_multi_kernel(
    const float4* __restrict__ s0, __half2* __restrict__ d0, int n0,
    const float4* __restrict__ s1, __half2* __restrict__ d1, int n1,
    const float4* __restrict__ s2, __half2* __restrict__ d2, int n2,
    const float4* __restrict__ s3, __half2* __restrict__ d3, int n3,
    const float4* __restrict__ s4, __half2* __restrict__ d4, int n4,
    const float* __restrict__ kva, __half* __restrict__ wkva, int n5)
{
    int i = blockIdx.x * blockDim.x + threadIdx.x;
    int j = i;
    if (j < n0) {
        float4 v = s0[j];
        d0[2*j+0] = __floats2half2_rn(v.x, v.y); d0[2*j+1] = __floats2half2_rn(v.z, v.w);
        return;
    }
    j -= n0;
    if (j < n1) {
        float4 v = s1[j];
        d1[2*j+0] = __floats2half2_rn(v.x, v.y); d1[2*j+1] = __floats2half2_rn(v.z, v.w);
        return;
    }
    j -= n1;
    if (j < n2) {
        float4 v = s2[j];
        d2[2*j+0] = __floats2half2_rn(v.x, v.y); d2[2*j+1] = __floats2half2_rn(v.z, v.w);
        return;
    }
    j -= n2;
    if (j < n3) {
        float4 v = s3[j];
        d3[2*j+0] = __floats2half2_rn(v.x, v.y); d3[2*j+1] = __floats2half2_rn(v.z, v.w);
        return;
    }
    j -= n3;
    if (j < n4) {
        float4 v = s4[j];
        d4[2*j+0] = __floats2half2_rn(v.x, v.y); d4[2*j+1] = __floats2half2_rn(v.z, v.w);
        return;
    }
    j -= n4;
    if (j < n5) {
        int k = (4 * j) / KVA_PAD, n = (4 * j) % KVA_PAD;
        __half2 lo, hi;
        if (n < CKV_W) {
            float4 v = *reinterpret_cast<const float4*>(kva + (size_t)k * CKV_W + n);
            lo = __floats2half2_rn(v.x, v.y); hi = __floats2half2_rn(v.z, v.w);
        } else {
            lo = __floats2half2_rn(0.f, 0.f); hi = lo;
        }
        __half2* dp = reinterpret_cast<__half2*>(wkva + (size_t)k * KVA_PAD + n);
        dp[0] = lo; dp[1] = hi;
    }
}

// ---------------- pipelined fp16 GEMM, dual problem sets ----------------
// BM=128, BN=256, BK=64, 512 threads, 3-stage cp.async (round-8 proven config)
#define A_STRH 72
#define B_STRH 264
#define A_SBYT (128 * A_STRH * 2)   // 18432
#define B_SBYT (64 * B_STRH * 2)    // 33792
#define STG_P  (A_SBYT + B_SBYT)    // 52224
#define SMEM_P (3 * STG_P)          // 156672

__global__ __launch_bounds__(512, 1)
void pgemm_kernel(const __half* __restrict__ A, int lda, int K,
                  const __half* __restrict__ B, int ldb,
                  float* __restrict__ C, int ldc, int N, int nt1,
                  const __half* __restrict__ A2, int lda2, int K2,
                  const __half* __restrict__ B2, int ldb2,
                  float* __restrict__ C2, int ldc2, int N2)
{
    int bx = blockIdx.x;
    if (bx >= nt1) {
        A = A2; lda = lda2; K = K2; B = B2; ldb = ldb2; C = C2; ldc = ldc2; N = N2;
        bx -= nt1;
    }
    const int row0 = blockIdx.y * 128;
    const int col0 = bx * 256;
    const int nk = K / 64;

    extern __shared__ char smem[];
    const uint32_t sb = smem_u32(smem);
    const int tid = threadIdx.x;
    const int wid = tid >> 5;
    const int wm  = wid >> 3;
    const int wn  = wid & 7;

    auto issue = [&](int t) {
        const int s = t % 3;
        const int k0 = t * 64;
        uint32_t ab = sb + s * STG_P;
        #pragma unroll
        for (int i = 0; i < 2; i++) {
            int idx = i * 512 + tid;
            int r = idx >> 3, c = idx & 7;
            cp16(ab + r * (A_STRH * 2) + c * 16, A + (size_t)(row0 + r) * lda + k0 + c * 8);
        }
        uint32_t bb = sb + s * STG_P + A_SBYT;
        #pragma unroll
        for (int i = 0; i < 4; i++) {
            int idx = i * 512 + tid;
            int kr = idx >> 5, c = idx & 31;
            cp16(bb + kr * (B_STRH * 2) + c * 16, B + (size_t)(k0 + kr) * ldb + col0 + c * 8);
        }
    };

    typedef wmma::fragment<wmma::matrix_a, 16, 16, 16, __half, wmma::row_major> AFrag;
    typedef wmma::fragment<wmma::matrix_b, 16, 16, 16, __half, wmma::row_major> BFrag;
    wmma::fragment<wmma::accumulator, 16, 16, 16, float> acc[4][2];
    #pragma unroll
    for (int i = 0; i < 4; i++)
        #pragma unroll
        for (int j = 0; j < 2; j++) wmma::fill_fragment(acc[i][j], 0.0f);

    issue(0); cp_commit();
    if (nk > 1) { issue(1); cp_commit(); }

    for (int t = 0; t < nk; t++) {
        if (t + 1 < nk) cp_wait<1>(); else cp_wait<0>();
        __syncthreads();
        if (t + 2 < nk) { issue(t + 2); cp_commit(); }

        const __half* As = reinterpret_cast<const __half*>(smem + (t % 3) * STG_P);
        const __half* Bs = reinterpret_cast<const __half*>(smem + (t % 3) * STG_P + A_SBYT);

        #pragma unroll
        for (int kk = 0; kk < 4; kk++) {
            AFrag af[4];
            BFrag bf[2];
            #pragma unroll
            for (int mf = 0; mf < 4; mf++)
                wmma::load_matrix_sync(af[mf], As + (wm * 64 + mf * 16) * A_STRH + kk * 16, A_STRH);
            #pragma unroll
            for (int nf = 0; nf < 2; nf++)
                wmma::load_matrix_sync(bf[nf], Bs + (kk * 16) * B_STRH + wn * 32 + nf * 16, B_STRH);
            #pragma unroll
            for (int mf = 0; mf < 4; mf++)
                #pragma unroll
                for (int nf = 0; nf < 2; nf++)
                    wmma::mma_sync(acc[mf][nf], af[mf], bf[nf], acc[mf][nf]);
        }
        __syncthreads();
    }

    #pragma unroll
    for (int mf = 0; mf < 4; mf++) {
        int gr = row0 + wm * 64 + mf * 16;
        #pragma unroll
        for (int nf = 0; nf < 2; nf++) {
            int gc = col0 + wn * 32 + nf * 16;
            if (gc + 16 <= N)
                wmma::store_matrix_sync(C + (size_t)gr * ldc + gc, acc[mf][nf], ldc,
                                        wmma::mem_row_major);
        }
    }
}

// ---------------- fused RMSNorm: grid.y 0 -> q_a, 1 -> ckv ----------------
__global__ __launch_bounds__(256)
void rms_fused_kernel(const float* __restrict__ qa, const float* __restrict__ wq,
                      const float* __restrict__ ckv, const float* __restrict__ wkv,
                      const float* __restrict__ cosT, const float* __restrict__ sinT,
                      const int* __restrict__ pos,
                      __half* __restrict__ qn, __half* __restrict__ cnorm,
                      float* __restrict__ kpe, float* __restrict__ cache)
{
    const int s = blockIdx.x;
    const int tid = threadIdx.x;
    __shared__ float sred[256];

    if (blockIdx.y == 0) {
        const float* x = qa + (size_t)s * QL_;
        __half*      y = qn + (size_t)s * QL_;
        float v[6];
        float local = 0.f;
        #pragma unroll
        for (int i = 0; i < 6; i++) { int c = tid + i * 256; v[i] = x[c]; local += v[i] * v[i]; }
        sred[tid] = local; __syncthreads();
        for (int st = 128; st > 0; st >>= 1) {
            if (tid < st) sred[tid] += sred[tid + st];
            __syncthreads();
        }
        float scale = rsqrtf(sred[0] / (float)QL_ + EPS_);
        #pragma unroll
        for (int i = 0; i < 6; i++) { int c = tid + i * 256; y[c] = __float2half(v[i] * scale * wq[c]); }
    } else {
        const float* x = ckv + (size_t)s * CKV_W;
        float v[2];
        float local = 0.f;
        #pragma unroll
        for (int i = 0; i < 2; i++) { int c = tid + i * 256; v[i] = x[c]; local += v[i] * v[i]; }
        sred[tid] = local; __syncthreads();
        for (int st = 128; st > 0; st >>= 1) {
            if (tid < st) sred[tid] += sred[tid + st];
            __syncthreads();
        }
        float scale = rsqrtf(sred[0] / (float)KVL_ + EPS_);
        #pragma unroll
        for (int i = 0; i < 2; i++) {
            int c = tid + i * 256;
            float y = v[i] * scale * wkv[c];
            cnorm[(size_t)s * KVL_ + c] = __float2half(y);
            cache[(size_t)s * CKV_W + c] = y;
        }
        if (tid < D_ROPE) {
            int p = pos[s];
            const float* cr = cosT + (size_t)p * D_ROPE;
            const float* sr = sinT + (size_t)p * D_ROPE;
            const float* t  = x + KVL_;
            int i = tid;
            float val;
            if (i < 32) val = t[2 * i] * cr[i] - t[2 * i + 1] * sr[i];
            else { int i2 = i - 32; val = t[2 * i2 + 1] * cr[i] + t[2 * i2] * sr[i]; }
            kpe[(size_t)s * D_ROPE + i] = val;
            cache[(size_t)s * CKV_W + KVL_ + i] = val;
        }
    }
}

// ---------------- fused assemble Q/K (perm16) + V transpose ----------------
__global__ __launch_bounds__(256)
void assemble_fused_kernel(const float* __restrict__ q, const float* __restrict__ kv,
                           const float* __restrict__ kpe,
                           const float* __restrict__ cosT, const float* __restrict__ sinT,
                           const int* __restrict__ pos,
                           __half* __restrict__ Q, __half* __restrict__ K,
                           __half* __restrict__ V)
{
    const int s0 = blockIdx.x * 64;
    const int h  = blockIdx.y;
    const int tid = threadIdx.x;

    #pragma unroll
    for (int it = 0; it < 48; it++) {
        int idx = it * 256 + tid;
        int sl = idx / QHEAD, d = idx % QHEAD;
        int s = s0 + sl;
        const float* qrow  = q  + (size_t)s * QDIM  + h * QHEAD;
        const float* kvrow = kv + (size_t)s * KVDIM + h * (D_NOPE + D_V);
        const size_t off = ((size_t)h * S_ + s) * QHEAD;

        float qv;
        if (d < D_NOPE) qv = qrow[d];
        else {
            int p = pos[s];
            const float* cr = cosT + (size_t)p * D_ROPE;
            const float* sr = sinT + (size_t)p * D_ROPE;
            const float* t  = qrow + D_NOPE;
            int i = d - D_NOPE;
            if (i < 32) qv = t[2 * i] * cr[i] - t[2 * i + 1] * sr[i];
            else { int i2 = i - 32; qv = t[2 * i2 + 1] * cr[i] + t[2 * i2] * sr[i]; }
        }
        float kvv = (d < D_NOPE) ? kvrow[d] : kpe[(size_t)s * D_ROPE + (d - D_NOPE)];
        int pd = perm16(d);
        Q[off + pd] = __float2half(qv);
        K[off + pd] = __float2half(kvv);
    }

    __shared__ float vt[64 * 132];
    #pragma unroll
    for (int i = 0; i < 32; i++) {
        int idx = i * 256 + tid;
        int sl = idx >> 7, d = idx & 127;
        vt[sl * 132 + d] = kv[(size_t)(s0 + sl) * KVDIM + h * (D_NOPE + D_V) + D_NOPE + d];
    }
    __syncthreads();
    #pragma unroll
    for (int i = 0; i < 32; i++) {
        int idx = i * 256 + tid;
        int d = idx >> 6, sl = idx & 63;
        V[((size_t)h * D_V + d) * S_ + s0 + perm16(sl)] = __float2half(vt[sl * 132 + d]);
    }
}

// ---------------- fused flash attention (fp16), heavy-CTA-first scheduling ----------------
#define QS_STR 200
#define KS_STR 200
#define VS_STR 40
#define SF_STR 36
#define PH_STR 40
#define QS_OFF 0
#define KS_OFF 25600
#define KS_BYTES 12800
#define VS_OFF (KS_OFF + 2*KS_BYTES)
#define VS_BYTES 10240
#define SF_OFF (VS_OFF + 2*VS_BYTES)
#define PH_OFF (SF_OFF + 64*SF_STR*4)
#define M_OFF  (PH_OFF + 64*PH_STR*2)
#define L_OFF  (M_OFF + 256)
#define AL_OFF (L_OFF + 256)
#define FLASH_SMEM (AL_OFF + 256)

__global__ __launch_bounds__(256, 2)
void flash_kernel(const __half* __restrict__ Q, const __half* __restrict__ K,
                  const __half* __restrict__ V, __half* __restrict__ attn)
{
    // Heaviest q-tiles (largest causal extent) launch first: low blockIdx.x -> high qt.
    const int qt = (S_ / 64 - 1) - blockIdx.x;
    const int h  = blockIdx.y;
    const int q0 = qt * 64;
    const int nt = 2 * qt + 2;

    extern __shared__ char sm[];
    const uint32_t sb = smem_u32(sm);
    float* mP = reinterpret_cast<float*>(sm + M_OFF);
    float* lP = reinterpret_cast<float*>(sm + L_OFF);
    float* aP = reinterpret_cast<float*>(sm + AL_OFF);

    const int tid = threadIdx.x;
    const int wid = tid >> 5;
    const int lid = tid & 31;
    const int gl  = lid >> 2;
    const int tg  = lid & 3;
    const int wm  = wid >> 2;
    const int wn  = wid & 3;

    const __half* Qg = Q + ((size_t)h * S_ + q0) * QHEAD;
    const __half* Kg = K + (size_t)h * S_ * QHEAD;
    const __half* Vg = V + (size_t)h * D_V * S_;

    auto issueKV = [&](int t, int st) {
        const __half* kp = Kg + (size_t)t * 32 * QHEAD;
        uint32_t kd = sb + KS_OFF + st * KS_BYTES;
        #pragma unroll
        for (int i = 0; i < 3; i++) {
            int idx = i * 256 + tid;
            int r = idx / 24, c = idx % 24;
            cp16(kd + r * (KS_STR * 2) + c * 16, kp + (size_t)r * QHEAD + c * 8);
        }
        uint32_t vd = sb + VS_OFF + st * VS_BYTES;
        #pragma unroll
        for (int i = 0; i < 2; i++) {
            int idx = i * 256 + tid;
            int d = idx >> 2, c = idx & 3;
            cp16(vd + d * (VS_STR * 2) + c * 16, Vg + (size_t)d * S_ + t * 32 + c * 8);
        }
    };

    #pragma unroll
    for (int i = 0; i < 6; i++) {
        int idx = i * 256 + tid;
        int r = idx / 24, c = idx % 24;
        cp16(sb + QS_OFF + r * (QS_STR * 2) + c * 16, Qg + (size_t)r * QHEAD + c * 8);
    }
    issueKV(0, 0);
    cp_commit();

    if (tid < 64) { mP[tid] = -1e30f; lP[tid] = 0.f; }

    float oacc[2][4][4];
    #pragma unroll
    for (int a = 0; a < 2; a++)
        #pragma unroll
        for (int b = 0; b < 4; b++)
            #pragma unroll
            for (int c = 0; c < 4; c++) oacc[a][b][c] = 0.f;

    const char* QsB = sm + QS_OFF;
    char* SfB = sm + SF_OFF;
    char* PhB = sm + PH_OFF;

    for (int t = 0; t < nt; t++) {
        const int st = t & 1;
        if (t + 1 < nt) { issueKV(t + 1, st ^ 1); cp_commit(); cp_wait<1>(); }
        else            { cp_wait<0>(); }
        __syncthreads();

        const char* KsB = sm + KS_OFF + st * KS_BYTES;
        float sacc[2][4] = {{0.f,0.f,0.f,0.f},{0.f,0.f,0.f,0.f}};
        const int bRow = wn * 8 + gl;
        #pragma unroll 4
        for (int kk = 0; kk < 12; kk++) {
            uint2 bb = *reinterpret_cast<const uint2*>(
                KsB + (bRow * KS_STR + kk * 16 + 4 * tg) * 2);
            #pragma unroll
            for (int mf = 0; mf < 2; mf++) {
                int r0 = wm * 32 + mf * 16 + gl;
                uint2 lo = *reinterpret_cast<const uint2*>(
                    QsB + (r0 * QS_STR + kk * 16 + 4 * tg) * 2);
                uint2 hi = *reinterpret_cast<const uint2*>(
                    QsB + ((r0 + 8) * QS_STR + kk * 16 + 4 * tg) * 2);
                mma16(sacc[mf], lo.x, hi.x, lo.y, hi.y, bb.x, bb.y);
            }
        }
        #pragma unroll
        for (int mf = 0; mf < 2; mf++) {
            int r0 = wm * 32 + mf * 16 + gl;
            int c0 = wn * 8 + 2 * tg;
            *reinterpret_cast<float2*>(SfB + (r0 * SF_STR + c0) * 4) =
                make_float2(sacc[mf][0], sacc[mf][1]);
            *reinterpret_cast<float2*>(SfB + ((r0 + 8) * SF_STR + c0) * 4) =
                make_float2(sacc[mf][2], sacc[mf][3]);
        }
        __syncthreads();

        {
            const int row = tid >> 2;
            const int cb  = (tid & 3) * 8;
            float* srow = reinterpret_cast<float*>(SfB) + row * SF_STR + cb;
            __half* prow = reinterpret_cast<__half*>(PhB) + row * PH_STR;
            float4 v0 = *reinterpret_cast<float4*>(srow);
            float4 v1 = *reinterpret_cast<float4*>(srow + 4);
            float v[8] = {v0.x, v0.y, v0.z, v0.w, v1.x, v1.y, v1.z, v1.w};
            const int rg = q0 + row;
            const int key0 = t * 32 + cb;
            const bool msk = (t >= 2 * qt);
            float mx = -1e30f;
            #pragma unroll
            for (int j = 0; j < 8; j++) {
                float val = v[j] * SCALE_;
                if (msk && (key0 + j) > rg) val = -1e30f;
                v[j] = val;
                mx = fmaxf(mx, val);
            }
            mx = fmaxf(mx, __shfl_xor_sync(0xffffffffu, mx, 1));
            mx = fmaxf(mx, __shfl_xor_sync(0xffffffffu, mx, 2));
            float mold = mP[row];
            float mnew = fmaxf(mold, mx);
            float al = __expf(mold - mnew);
            float sum = 0.f;
            #pragma unroll
            for (int j = 0; j < 8; j++) {
                float p = __expf(v[j] - mnew);
                sum += p;
                prow[perm16(cb + j)] = __float2half(p);
            }
            sum += __shfl_xor_sync(0xffffffffu, sum, 1);
            sum += __shfl_xor_sync(0xffffffffu, sum, 2);
            if ((tid & 3) == 0) {
                mP[row] = mnew;
                lP[row] = lP[row] * al + sum;
                aP[row] = al;
            }
        }
        __syncthreads();

        const char* VsB = sm + VS_OFF + st * VS_BYTES;
        #pragma unroll
        for (int mf = 0; mf < 2; mf++) {
            int r0 = wm * 32 + mf * 16 + gl;
            float a0 = aP[r0], a8 = aP[r0 + 8];
            #pragma unroll
            for (int nf = 0; nf < 4; nf++) {
                oacc[mf][nf][0] *= a0; oacc[mf][nf][1] *= a0;
                oacc[mf][nf][2] *= a8; oacc[mf][nf][3] *= a8;
            }
        }
        #pragma unroll
        for (int kk = 0; kk < 2; kk++) {
            uint2 alo[2], ahi[2];
            #pragma unroll
            for (int mf = 0; mf < 2; mf++) {
                int r0 = wm * 32 + mf * 16 + gl;
                alo[mf] = *reinterpret_cast<const uint2*>(
                    PhB + (r0 * PH_STR + kk * 16 + 4 * tg) * 2);
                ahi[mf] = *reinterpret_cast<const uint2*>(
                    PhB + ((r0 + 8) * PH_STR + kk * 16 + 4 * tg) * 2);
            }
            #pragma unroll
            for (int nf = 0; nf < 4; nf++) {
                int nc = wn * 32 + nf * 8 + gl;
                uint2 bv = *reinterpret_cast<const uint2*>(
                    VsB + (nc * VS_STR + kk * 16 + 4 * tg) * 2);
                #pragma unroll
                for (int mf = 0; mf < 2; mf++)
                    mma16(oacc[mf][nf], alo[mf].x, ahi[mf].x, alo[mf].y, ahi[mf].y, bv.x, bv.y);
            }
        }
        __syncthreads();
    }

    #pragma unroll
    for (int mf = 0; mf < 2; mf++) {
        int r0 = wm * 32 + mf * 16 + gl;
        float inv0 = 1.f / lP[r0];
        float inv8 = 1.f / lP[r0 + 8];
        #pragma unroll
        for (int nf = 0; nf < 4; nf++) {
            int col = h * D_V + wn * 32 + nf * 8 + 2 * tg;
            __half2* o0 = reinterpret_cast<__half2*>(attn + (size_t)(q0 + r0) * (H_ * D_V) + col);
            __half2* o8 = reinterpret_cast<__half2*>(attn + (size_t)(q0 + r0 + 8) * (H_ * D_V) + col);
            *o0 = __floats2half2_rn(oacc[mf][nf][0] * inv0, oacc[mf][nf][1] * inv0);
            *o8 = __floats2half2_rn(oacc[mf][nf][2] * inv8, oacc[mf][nf][3] * inv8);
        }
    }
}

// ---------------- host launch ----------------
extern "C" void kernel_launch(void* const* d_in, const int* in_sizes, int n_in,
                              void* d_out, int out_size)
{
    const float* x       = (const float*)d_in[0];
    const int*   pos     = (const int*)  d_in[2];
    const float* cosT    = (const float*)d_in[3];
    const float* sinT    = (const float*)d_in[4];
    const float* q_a_w   = (const float*)d_in[5];
    const float* q_a_ln  = (const float*)d_in[6];
    const float* q_b_w   = (const float*)d_in[7];
    const float* kv_a_w  = (const float*)d_in[8];
    const float* kv_a_ln = (const float*)d_in[9];
    const float* kv_b_w  = (const float*)d_in[10];
    const float* o_w     = (const float*)d_in[11];
    float* out = (float*)d_out;
    float* out_cache = out + (size_t)S_ * HID_;

    __half *xc, *wqa, *wqb, *wkva, *wkvb, *wo, *qn, *cnorm, *Q, *K, *V, *attn;
    float *qa, *ckv, *kpe, *q, *kv;
    cudaGetSymbolAddress((void**)&xc,     g_x);
    cudaGetSymbolAddress((void**)&wqa,    g_wqa);
    cudaGetSymbolAddress((void**)&wqb,    g_wqb);
    cudaGetSymbolAddress((void**)&wkva,   g_wkva);
    cudaGetSymbolAddress((void**)&wkvb,   g_wkvb);
    cudaGetSymbolAddress((void**)&wo,     g_wo);
    cudaGetSymbolAddress((void**)&qa,     g_qa);
    cudaGetSymbolAddress((void**)&qn,     g_qn);
    cudaGetSymbolAddress((void**)&ckv,    g_ckv);
    cudaGetSymbolAddress((void**)&cnorm,  g_cnorm);
    cudaGetSymbolAddress((void**)&kpe,    g_kpe);
    cudaGetSymbolAddress((void**)&q,      g_q);
    cudaGetSymbolAddress((void**)&kv,     g_kv);
    cudaGetSymbolAddress((void**)&Q,      g_Q);
    cudaGetSymbolAddress((void**)&K,      g_K);
    cudaGetSymbolAddress((void**)&V,      g_V);
    cudaGetSymbolAddress((void**)&attn,   g_attn);

    cudaFuncSetAttribute(pgemm_kernel, cudaFuncAttributeMaxDynamicSharedMemorySize, SMEM_P);
    cudaFuncSetAttribute(flash_kernel, cudaFuncAttributeMaxDynamicSharedMemorySize, FLASH_SMEM);

    // prep: all conversions in 1 launch
    {
        int n0 = S_ * HID_ / 4, n1 = HID_ * QL_ / 4, n2 = QL_ * QDIM / 4,
            n3 = KVL_ * KVDIM / 4, n4 = H_ * D_V * HID_ / 4,
            n5 = HID_ * KVA_PAD / 4;
        int total = n0 + n1 + n2 + n3 + n4 + n5;
        conv_multi_kernel<<<(total + 255) / 256, 256>>>(
            (const float4*)x,      (__half2*)xc,   n0,
            (const float4*)q_a_w,  (__half2*)wqa,  n1,
            (const float4*)q_b_w,  (__half2*)wqb,  n2,
            (const float4*)kv_b_w, (__half2*)wkvb, n3,
            (const float4*)o_w,    (__half2*)wo,   n4,
            kv_a_w, wkva, n5);
    }

    dim3 blk5(512);

    // 1) fused: qa = x@q_a_w (6 tiles) ; ckv = x@kv_a_w (3 tiles, padded)
    pgemm_kernel<<<dim3(9, S_/128), blk5, SMEM_P>>>(
        xc, HID_, HID_, wqa, QL_, qa, QL_, QL_, 6,
        xc, HID_, HID_, wkva, KVA_PAD, ckv, CKV_W, CKV_W);
    // 2) fused RMSNorms
    rms_fused_kernel<<<dim3(S_, 2), 256>>>(qa, q_a_ln, ckv, kv_a_ln, cosT, sinT, pos,
                                           qn, cnorm, kpe, out_cache);
    // 3) fused: q = qn@q_b_w (12 tiles, K=1536) ; kv = cnorm@kv_b_w (16 tiles, K=512)
    pgemm_kernel<<<dim3(28, S_/128), blk5, SMEM_P>>>(
        qn, QL_, QL_, wqb, QDIM, q, QDIM, QDIM, 12,
        cnorm, KVL_, KVL_, wkvb, KVDIM, kv, KVDIM, KVDIM);
    // 4) fused assemble Q/K + V transpose
    assemble_fused_kernel<<<dim3(S_/64, H_), 256>>>(q, kv, kpe, cosT, sinT, pos, Q, K, V);
    // 5) fused flash attention (heavy tiles first)
    flash_kernel<<<dim3(S_/64, H_), 256, FLASH_SMEM>>>(Q, K, V, attn);
    // 6) out = attn @ o_w
    pgemm_kernel<<<dim3(HID_/256, S_/128), blk5, SMEM_P>>>(
        attn, H_*D_V, H_*D_V, wo, HID_, out, HID_, HID_, HID_/256,
        nullptr, 0, 0, nullptr, 0, nullptr, 0, 0);
}

// round 11
// speedup vs baseline: 1.0437x; 1.0158x over previous
#include <cuda_runtime.h>
#include <cuda_fp16.h>
#include <mma.h>
#include <math.h>
#include <stdint.h>

using namespace nvcuda;

// ---------------- problem constants ----------------
#define S_      2048
#define HID_    2048
#define H_      16
#define D_NOPE  128
#define D_ROPE  64
#define D_V     128
#define QHEAD   192
#define QL_     1536
#define KVL_    512
#define CKV_W   576
#define KVA_PAD 768
#define QDIM    3072
#define KVDIM   4096
#define EPS_    1e-6f
#define SCALE_  0.07216878364870322f

// ---------------- scratch ----------------
__device__ __half g_x     [S_ * HID_];
__device__ __half g_wqa   [HID_ * QL_];
__device__ __half g_wqb   [QL_ * QDIM];
__device__ __half g_wkva  [HID_ * KVA_PAD];
__device__ __half g_wkvb  [KVL_ * KVDIM];
__device__ __half g_wo    [H_ * D_V * HID_];
__device__ float  g_qa    [S_ * QL_];
__device__ __half g_qn    [S_ * QL_];
__device__ float  g_ckv   [S_ * CKV_W];
__device__ __half g_cnorm [S_ * KVL_];
__device__ float  g_kpe   [S_ * D_ROPE];
__device__ float  g_q     [S_ * QDIM];
__device__ float  g_kv    [S_ * KVDIM];
__device__ __half g_Q     [H_ * S_ * QHEAD];
__device__ __half g_K     [H_ * S_ * QHEAD];
__device__ __half g_V     [H_ * D_V * S_];
__device__ __half g_attn  [S_ * (H_ * D_V)];

__device__ __forceinline__ int perm16(int c) {
    int j = c & 15;
    return (c & ~15) | (((j >> 1) & 3) << 2) | ((j >> 3) << 1) | (j & 1);
}
__device__ __forceinline__ uint32_t smem_u32(const void* p) {
    uint32_t a;
    asm("{ .reg .u64 t; cvta.to.shared.u64 t, %1; cvt.u32.u64 %0, t; }" : "=r"(a) : "l"(p));
    return a;
}
__device__ __forceinline__ void cp16(uint32_t d, const void* s) {
    asm volatile("cp.async.ca.shared.global [%0], [%1], 16;" :: "r"(d), "l"(s));
}
__device__ __forceinline__ void cp_commit() {
    asm volatile("cp.async.commit_group;" ::: "memory");
}
template<int N> __device__ __forceinline__ void cp_wait() {
    asm volatile("cp.async.wait_group %0;" :: "n"(N) : "memory");
}
__device__ __forceinline__ void mma16(float* c, uint32_t a0, uint32_t a1, uint32_t a2, uint32_t a3,
                                      uint32_t b0, uint32_t b1) {
    asm volatile(
        "mma.sync.aligned.m16n8k16.row.col.f32.f16.f16.f32 "
        "{%0,%1,%2,%3}, {%4,%5,%6,%7}, {%8,%9}, {%0,%1,%2,%3};"
        : "+f"(c[0]), "+f"(c[1]), "+f"(c[2]), "+f"(c[3])
        : "r"(a0), "r"(a1), "r"(a2), "r"(a3), "r"(b0), "r"(b1));
}

// ---------------- prep: fused fp16 conversion (5 tensors + padded kv_a, 1 launch) ----------------
__global__ void conv_multi_kernel(
    const float4* __restrict__ s0, __half2* __restrict__ d0, int n0,
    const float4* __restrict__ s1, __half2* __restrict__ d1, int n1,
    const float4* __restrict__ s2, __half2* __restrict__ d2, int n2,
    const float4* __restrict__ s3, __half2* __restrict__ d3, int n3,
    const float4* __restrict__ s4, __half2* __restrict__ d4, int n4,
    const float* __restrict__ kva, __half* __restrict__ wkva, int n5)
{
    int i = blockIdx.x * blockDim.x + threadIdx.x;
    int j = i;
    if (j < n0) {
        float4 v = s0[j];
        d0[2*j+0] = __floats2half2_rn(v.x, v.y); d0[2*j+1] = __floats2half2_rn(v.z, v.w);
        return;
    }
    j -= n0;
    if (j < n1) {
        float4 v = s1[j];
        d1[2*j+0] = __floats2half2_rn(v.x, v.y); d1[2*j+1] = __floats2half2_rn(v.z, v.w);
        return;
    }
    j -= n1;
    if (j < n2) {
        float4 v = s2[j];
        d2[2*j+0] = __floats2half2_rn(v.x, v.y); d2[2*j+1] = __floats2half2_rn(v.z, v.w);
        return;
    }
    j -= n2;
    if (j < n3) {
        float4 v = s3[j];
        d3[2*j+0] = __floats2half2_rn(v.x, v.y); d3[2*j+1] = __floats2half2_rn(v.z, v.w);
        return;
    }
    j -= n3;
    if (j < n4) {
        float4 v = s4[j];
        d4[2*j+0] = __floats2half2_rn(v.x, v.y); d4[2*j+1] = __floats2half2_rn(v.z, v.w);
        return;
    }
    j -= n4;
    if (j < n5) {
        int k = (4 * j) / KVA_PAD, n = (4 * j) % KVA_PAD;
        __half2 lo, hi;
        if (n < CKV_W) {
            float4 v = *reinterpret_cast<const float4*>(kva + (size_t)k * CKV_W + n);
            lo = __floats2half2_rn(v.x, v.y); hi = __floats2half2_rn(v.z, v.w);
        } else {
            lo = __floats2half2_rn(0.f, 0.f); hi = lo;
        }
        __half2* dp = reinterpret_cast<__half2*>(wkva + (size_t)k * KVA_PAD + n);
        dp[0] = lo; dp[1] = hi;
    }
}

// ---------------- pipelined fp16 GEMM, dual problem sets ----------------
// BM=128, BN=256, BK=64, 512 threads, 3-stage cp.async, single barrier per k-tile
#define A_STRH 72
#define B_STRH 264
#define A_SBYT (128 * A_STRH * 2)   // 18432
#define B_SBYT (64 * B_STRH * 2)    // 33792
#define STG_P  (A_SBYT + B_SBYT)    // 52224
#define SMEM_P (3 * STG_P)          // 156672

__global__ __launch_bounds__(512, 1)
void pgemm_kernel(const __half* __restrict__ A, int lda, int K,
                  const __half* __restrict__ B, int ldb,
                  float* __restrict__ C, int ldc, int N, int nt1,
                  const __half* __restrict__ A2, int lda2, int K2,
                  const __half* __restrict__ B2, int ldb2,
                  float* __restrict__ C2, int ldc2, int N2)
{
    int bx = blockIdx.x;
    if (bx >= nt1) {
        A = A2; lda = lda2; K = K2; B = B2; ldb = ldb2; C = C2; ldc = ldc2; N = N2;
        bx -= nt1;
    }
    const int row0 = blockIdx.y * 128;
    const int col0 = bx * 256;
    const int nk = K / 64;

    extern __shared__ char smem[];
    const uint32_t sb = smem_u32(smem);
    const int tid = threadIdx.x;
    const int wid = tid >> 5;
    const int wm  = wid >> 3;
    const int wn  = wid & 7;

    auto issue = [&](int t) {
        const int s = t % 3;
        const int k0 = t * 64;
        uint32_t ab = sb + s * STG_P;
        #pragma unroll
        for (int i = 0; i < 2; i++) {
            int idx = i * 512 + tid;
            int r = idx >> 3, c = idx & 7;
            cp16(ab + r * (A_STRH * 2) + c * 16, A + (size_t)(row0 + r) * lda + k0 + c * 8);
        }
        uint32_t bb = sb + s * STG_P + A_SBYT;
        #pragma unroll
        for (int i = 0; i < 4; i++) {
            int idx = i * 512 + tid;
            int kr = idx >> 5, c = idx & 31;
            cp16(bb + kr * (B_STRH * 2) + c * 16, B + (size_t)(k0 + kr) * ldb + col0 + c * 8);
        }
    };

    typedef wmma::fragment<wmma::matrix_a, 16, 16, 16, __half, wmma::row_major> AFrag;
    typedef wmma::fragment<wmma::matrix_b, 16, 16, 16, __half, wmma::row_major> BFrag;
    wmma::fragment<wmma::accumulator, 16, 16, 16, float> acc[4][2];
    #pragma unroll
    for (int i = 0; i < 4; i++)
        #pragma unroll
        for (int j = 0; j < 2; j++) wmma::fill_fragment(acc[i][j], 0.0f);

    issue(0); cp_commit();
    if (nk > 1) { issue(1); cp_commit(); }

    for (int t = 0; t < nk; t++) {
        if (t + 1 < nk) cp_wait<1>(); else cp_wait<0>();
        __syncthreads();
        // Refill of slot (t+2)%3 == (t-1)%3 is safe here: every warp's reads of
        // that slot (iter t-1) precede its arrival at the barrier above.
        if (t + 2 < nk) { issue(t + 2); cp_commit(); }

        const __half* As = reinterpret_cast<const __half*>(smem + (t % 3) * STG_P);
        const __half* Bs = reinterpret_cast<const __half*>(smem + (t % 3) * STG_P + A_SBYT);

        #pragma unroll
        for (int kk = 0; kk < 4; kk++) {
            AFrag af[4];
            BFrag bf[2];
            #pragma unroll
            for (int mf = 0; mf < 4; mf++)
                wmma::load_matrix_sync(af[mf], As + (wm * 64 + mf * 16) * A_STRH + kk * 16, A_STRH);
            #pragma unroll
            for (int nf = 0; nf < 2; nf++)
                wmma::load_matrix_sync(bf[nf], Bs + (kk * 16) * B_STRH + wn * 32 + nf * 16, B_STRH);
            #pragma unroll
            for (int mf = 0; mf < 4; mf++)
                #pragma unroll
                for (int nf = 0; nf < 2; nf++)
                    wmma::mma_sync(acc[mf][nf], af[mf], bf[nf], acc[mf][nf]);
        }
        // no bottom barrier: top barrier of next iter orders slot reuse
    }

    #pragma unroll
    for (int mf = 0; mf < 4; mf++) {
        int gr = row0 + wm * 64 + mf * 16;
        #pragma unroll
        for (int nf = 0; nf < 2; nf++) {
            int gc = col0 + wn * 32 + nf * 16;
            if (gc + 16 <= N)
                wmma::store_matrix_sync(C + (size_t)gr * ldc + gc, acc[mf][nf], ldc,
                                        wmma::mem_row_major);
        }
    }
}

// ---------------- fused RMSNorm: grid.y 0 -> q_a, 1 -> ckv ----------------
__global__ __launch_bounds__(256)
void rms_fused_kernel(const float* __restrict__ qa, const float* __restrict__ wq,
                      const float* __restrict__ ckv, const float* __restrict__ wkv,
                      const float* __restrict__ cosT, const float* __restrict__ sinT,
                      const int* __restrict__ pos,
                      __half* __restrict__ qn, __half* __restrict__ cnorm,
                      float* __restrict__ kpe, float* __restrict__ cache)
{
    const int s = blockIdx.x;
    const int tid = threadIdx.x;
    __shared__ float sred[256];

    if (blockIdx.y == 0) {
        const float* x = qa + (size_t)s * QL_;
        __half*      y = qn + (size_t)s * QL_;
        float v[6];
        float local = 0.f;
        #pragma unroll
        for (int i = 0; i < 6; i++) { int c = tid + i * 256; v[i] = x[c]; local += v[i] * v[i]; }
        sred[tid] = local; __syncthreads();
        for (int st = 128; st > 0; st >>= 1) {
            if (tid < st) sred[tid] += sred[tid + st];
            __syncthreads();
        }
        float scale = rsqrtf(sred[0] / (float)QL_ + EPS_);
        #pragma unroll
        for (int i = 0; i < 6; i++) { int c = tid + i * 256; y[c] = __float2half(v[i] * scale * wq[c]); }
    } else {
        const float* x = ckv + (size_t)s * CKV_W;
        float v[2];
        float local = 0.f;
        #pragma unroll
        for (int i = 0; i < 2; i++) { int c = tid + i * 256; v[i] = x[c]; local += v[i] * v[i]; }
        sred[tid] = local; __syncthreads();
        for (int st = 128; st > 0; st >>= 1) {
            if (tid < st) sred[tid] += sred[tid + st];
            __syncthreads();
        }
        float scale = rsqrtf(sred[0] / (float)KVL_ + EPS_);
        #pragma unroll
        for (int i = 0; i < 2; i++) {
            int c = tid + i * 256;
            float y = v[i] * scale * wkv[c];
            cnorm[(size_t)s * KVL_ + c] = __float2half(y);
            cache[(size_t)s * CKV_W + c] = y;
        }
        if (tid < D_ROPE) {
            int p = pos[s];
            const float* cr = cosT + (size_t)p * D_ROPE;
            const float* sr = sinT + (size_t)p * D_ROPE;
            const float* t  = x + KVL_;
            int i = tid;
            float val;
            if (i < 32) val = t[2 * i] * cr[i] - t[2 * i + 1] * sr[i];
            else { int i2 = i - 32; val = t[2 * i2 + 1] * cr[i] + t[2 * i2] * sr[i]; }
            kpe[(size_t)s * D_ROPE + i] = val;
            cache[(size_t)s * CKV_W + KVL_ + i] = val;
        }
    }
}

// ---------------- fused assemble Q/K (perm16) + V transpose ----------------
__global__ __launch_bounds__(256)
void assemble_fused_kernel(const float* __restrict__ q, const float* __restrict__ kv,
                           const float* __restrict__ kpe,
                           const float* __restrict__ cosT, const float* __restrict__ sinT,
                           const int* __restrict__ pos,
                           __half* __restrict__ Q, __half* __restrict__ K,
                           __half* __restrict__ V)
{
    const int s0 = blockIdx.x * 64;
    const int h  = blockIdx.y;
    const int tid = threadIdx.x;

    #pragma unroll
    for (int it = 0; it < 48; it++) {
        int idx = it * 256 + tid;
        int sl = idx / QHEAD, d = idx % QHEAD;
        int s = s0 + sl;
        const float* qrow  = q  + (size_t)s * QDIM  + h * QHEAD;
        const float* kvrow = kv + (size_t)s * KVDIM + h * (D_NOPE + D_V);
        const size_t off = ((size_t)h * S_ + s) * QHEAD;

        float qv;
        if (d < D_NOPE) qv = qrow[d];
        else {
            int p = pos[s];
            const float* cr = cosT + (size_t)p * D_ROPE;
            const float* sr = sinT + (size_t)p * D_ROPE;
            const float* t  = qrow + D_NOPE;
            int i = d - D_NOPE;
            if (i < 32) qv = t[2 * i] * cr[i] - t[2 * i + 1] * sr[i];
            else { int i2 = i - 32; qv = t[2 * i2 + 1] * cr[i] + t[2 * i2] * sr[i]; }
        }
        float kvv = (d < D_NOPE) ? kvrow[d] : kpe[(size_t)s * D_ROPE + (d - D_NOPE)];
        int pd = perm16(d);
        Q[off + pd] = __float2half(qv);
        K[off + pd] = __float2half(kvv);
    }

    __shared__ float vt[64 * 132];
    #pragma unroll
    for (int i = 0; i < 32; i++) {
        int idx = i * 256 + tid;
        int sl = idx >> 7, d = idx & 127;
        vt[sl * 132 + d] = kv[(size_t)(s0 + sl) * KVDIM + h * (D_NOPE + D_V) + D_NOPE + d];
    }
    __syncthreads();
    #pragma unroll
    for (int i = 0; i < 32; i++) {
        int idx = i * 256 + tid;
        int d = idx >> 6, sl = idx & 63;
        V[((size_t)h * D_V + d) * S_ + s0 + perm16(sl)] = __float2half(vt[sl * 132 + d]);
    }
}

// ---------------- fused flash attention (fp16) ----------------
#define QS_STR 200
#define KS_STR 200
#define VS_STR 40
#define SF_STR 36
#define PH_STR 40
#define QS_OFF 0
#define KS_OFF 25600
#define KS_BYTES 12800
#define VS_OFF (KS_OFF + 2*KS_BYTES)
#define VS_BYTES 10240
#define SF_OFF (VS_OFF + 2*VS_BYTES)
#define PH_OFF (SF_OFF + 64*SF_STR*4)
#define M_OFF  (PH_OFF + 64*PH_STR*2)
#define L_OFF  (M_OFF + 256)
#define AL_OFF (L_OFF + 256)
#define FLASH_SMEM (AL_OFF + 256)

__global__ __launch_bounds__(256, 2)
void flash_kernel(const __half* __restrict__ Q, const __half* __restrict__ K,
                  const __half* __restrict__ V, __half* __restrict__ attn)
{
    const int qt = blockIdx.x;
    const int h  = blockIdx.y;
    const int q0 = qt * 64;
    const int nt = 2 * qt + 2;

    extern __shared__ char sm[];
    const uint32_t sb = smem_u32(sm);
    float* mP = reinterpret_cast<float*>(sm + M_OFF);
    float* lP = reinterpret_cast<float*>(sm + L_OFF);
    float* aP = reinterpret_cast<float*>(sm + AL_OFF);

    const int tid = threadIdx.x;
    const int wid = tid >> 5;
    const int lid = tid & 31;
    const int gl  = lid >> 2;
    const int tg  = lid & 3;
    const int wm  = wid >> 2;
    const int wn  = wid & 3;

    const __half* Qg = Q + ((size_t)h * S_ + q0) * QHEAD;
    const __half* Kg = K + (size_t)h * S_ * QHEAD;
    const __half* Vg = V + (size_t)h * D_V * S_;

    auto issueKV = [&](int t, int st) {
        const __half* kp = Kg + (size_t)t * 32 * QHEAD;
        uint32_t kd = sb + KS_OFF + st * KS_BYTES;
        #pragma unroll
        for (int i = 0; i < 3; i++) {
            int idx = i * 256 + tid;
            int r = idx / 24, c = idx % 24;
            cp16(kd + r * (KS_STR * 2) + c * 16, kp + (size_t)r * QHEAD + c * 8);
        }
        uint32_t vd = sb + VS_OFF + st * VS_BYTES;
        #pragma unroll
        for (int i = 0; i < 2; i++) {
            int idx = i * 256 + tid;
            int d = idx >> 2, c = idx & 3;
            cp16(vd + d * (VS_STR * 2) + c * 16, Vg + (size_t)d * S_ + t * 32 + c * 8);
        }
    };

    #pragma unroll
    for (int i = 0; i < 6; i++) {
        int idx = i * 256 + tid;
        int r = idx / 24, c = idx % 24;
        cp16(sb + QS_OFF + r * (QS_STR * 2) + c * 16, Qg + (size_t)r * QHEAD + c * 8);
    }
    issueKV(0, 0);
    cp_commit();

    if (tid < 64) { mP[tid] = -1e30f; lP[tid] = 0.f; }

    float oacc[2][4][4];
    #pragma unroll
    for (int a = 0; a < 2; a++)
        #pragma unroll
        for (int b = 0; b < 4; b++)
            #pragma unroll
            for (int c = 0; c < 4; c++) oacc[a][b][c] = 0.f;

    const char* QsB = sm + QS_OFF;
    char* SfB = sm + SF_OFF;
    char* PhB = sm + PH_OFF;

    for (int t = 0; t < nt; t++) {
        const int st = t & 1;
        if (t + 1 < nt) { issueKV(t + 1, st ^ 1); cp_commit(); cp_wait<1>(); }
        else            { cp_wait<0>(); }
        __syncthreads();

        const char* KsB = sm + KS_OFF + st * KS_BYTES;
        float sacc[2][4] = {{0.f,0.f,0.f,0.f},{0.f,0.f,0.f,0.f}};
        const int bRow = wn * 8 + gl;
        #pragma unroll 4
        for (int kk = 0; kk < 12; kk++) {
            uint2 bb = *reinterpret_cast<const uint2*>(
                KsB + (bRow * KS_STR + kk * 16 + 4 * tg) * 2);
            #pragma unroll
            for (int mf = 0; mf < 2; mf++) {
                int r0 = wm * 32 + mf * 16 + gl;
                uint2 lo = *reinterpret_cast<const uint2*>(
                    QsB + (r0 * QS_STR + kk * 16 + 4 * tg) * 2);
                uint2 hi = *reinterpret_cast<const uint2*>(
                    QsB + ((r0 + 8) * QS_STR + kk * 16 + 4 * tg) * 2);
                mma16(sacc[mf], lo.x, hi.x, lo.y, hi.y, bb.x, bb.y);
            }
        }
        #pragma unroll
        for (int mf = 0; mf < 2; mf++) {
            int r0 = wm * 32 + mf * 16 + gl;
            int c0 = wn * 8 + 2 * tg;
            *reinterpret_cast<float2*>(SfB + (r0 * SF_STR + c0) * 4) =
                make_float2(sacc[mf][0], sacc[mf][1]);
            *reinterpret_cast<float2*>(SfB + ((r0 + 8) * SF_STR + c0) * 4) =
                make_float2(sacc[mf][2], sacc[mf][3]);
        }
        __syncthreads();

        {
            const int row = tid >> 2;
            const int cb  = (tid & 3) * 8;
            float* srow = reinterpret_cast<float*>(SfB) + row * SF_STR + cb;
            __half* prow = reinterpret_cast<__half*>(PhB) + row * PH_STR;
            float4 v0 = *reinterpret_cast<float4*>(srow);
            float4 v1 = *reinterpret_cast<float4*>(srow + 4);
            float v[8] = {v0.x, v0.y, v0.z, v0.w, v1.x, v1.y, v1.z, v1.w};
            const int rg = q0 + row;
            const int key0 = t * 32 + cb;
            const bool msk = (t >= 2 * qt);
            float mx = -1e30f;
            #pragma unroll
            for (int j = 0; j < 8; j++) {
                float val = v[j] * SCALE_;
                if (msk && (key0 + j) > rg) val = -1e30f;
                v[j] = val;
                mx = fmaxf(mx, val);
            }
            mx = fmaxf(mx, __shfl_xor_sync(0xffffffffu, mx, 1));
            mx = fmaxf(mx, __shfl_xor_sync(0xffffffffu, mx, 2));
            float mold = mP[row];
            float mnew = fmaxf(mold, mx);
            float al = __expf(mold - mnew);
            float sum = 0.f;
            #pragma unroll
            for (int j = 0; j < 8; j++) {
                float p = __expf(v[j] - mnew);
                sum += p;
                prow[perm16(cb + j)] = __float2half(p);
            }
            sum += __shfl_xor_sync(0xffffffffu, sum, 1);
            sum += __shfl_xor_sync(0xffffffffu, sum, 2);
            if ((tid & 3) == 0) {
                mP[row] = mnew;
                lP[row] = lP[row] * al + sum;
                aP[row] = al;
            }
        }
        __syncthreads();

        const char* VsB = sm + VS_OFF + st * VS_BYTES;
        #pragma unroll
        for (int mf = 0; mf < 2; mf++) {
            int r0 = wm * 32 + mf * 16 + gl;
            float a0 = aP[r0], a8 = aP[r0 + 8];
            #pragma unroll
            for (int nf = 0; nf < 4; nf++) {
                oacc[mf][nf][0] *= a0; oacc[mf][nf][1] *= a0;
                oacc[mf][nf][2] *= a8; oacc[mf][nf][3] *= a8;
            }
        }
        #pragma unroll
        for (int kk = 0; kk < 2; kk++) {
            uint2 alo[2], ahi[2];
            #pragma unroll
            for (int mf = 0; mf < 2; mf++) {
                int r0 = wm * 32 + mf * 16 + gl;
                alo[mf] = *reinterpret_cast<const uint2*>(
                    PhB + (r0 * PH_STR + kk * 16 + 4 * tg) * 2);
                ahi[mf] = *reinterpret_cast<const uint2*>(
                    PhB + ((r0 + 8) * PH_STR + kk * 16 + 4 * tg) * 2);
            }
            #pragma unroll
            for (int nf = 0; nf < 4; nf++) {
                int nc = wn * 32 + nf * 8 + gl;
                uint2 bv = *reinterpret_cast<const uint2*>(
                    VsB + (nc * VS_STR + kk * 16 + 4 * tg) * 2);
                #pragma unroll
                for (int mf = 0; mf < 2; mf++)
                    mma16(oacc[mf][nf], alo[mf].x, ahi[mf].x, alo[mf].y, ahi[mf].y, bv.x, bv.y);
            }
        }
        __syncthreads();
    }

    #pragma unroll
    for (int mf = 0; mf < 2; mf++) {
        int r0 = wm * 32 + mf * 16 + gl;
        float inv0 = 1.f / lP[r0];
        float inv8 = 1.f / lP[r0 + 8];
        #pragma unroll
        for (int nf = 0; nf < 4; nf++) {
            int col = h * D_V + wn * 32 + nf * 8 + 2 * tg;
            __half2* o0 = reinterpret_cast<__half2*>(attn + (size_t)(q0 + r0) * (H_ * D_V) + col);
            __half2* o8 = reinterpret_cast<__half2*>(attn + (size_t)(q0 + r0 + 8) * (H_ * D_V) + col);
            *o0 = __floats2half2_rn(oacc[mf][nf][0] * inv0, oacc[mf][nf][1] * inv0);
            *o8 = __floats2half2_rn(oacc[mf][nf][2] * inv8, oacc[mf][nf][3] * inv8);
        }
    }
}

// ---------------- host launch ----------------
extern "C" void kernel_launch(void* const* d_in, const int* in_sizes, int n_in,
                              void* d_out, int out_size)
{
    const float* x       = (const float*)d_in[0];
    const int*   pos     = (const int*)  d_in[2];
    const float* cosT    = (const float*)d_in[3];
    const float* sinT    = (const float*)d_in[4];
    const float* q_a_w   = (const float*)d_in[5];
    const float* q_a_ln  = (const float*)d_in[6];
    const float* q_b_w   = (const float*)d_in[7];
    const float* kv_a_w  = (const float*)d_in[8];
    const float* kv_a_ln = (const float*)d_in[9];
    const float* kv_b_w  = (const float*)d_in[10];
    const float* o_w     = (const float*)d_in[11];
    float* out = (float*)d_out;
    float* out_cache = out + (size_t)S_ * HID_;

    __half *xc, *wqa, *wqb, *wkva, *wkvb, *wo, *qn, *cnorm, *Q, *K, *V, *attn;
    float *qa, *ckv, *kpe, *q, *kv;
    cudaGetSymbolAddress((void**)&xc,     g_x);
    cudaGetSymbolAddress((void**)&wqa,    g_wqa);
    cudaGetSymbolAddress((void**)&wqb,    g_wqb);
    cudaGetSymbolAddress((void**)&wkva,   g_wkva);
    cudaGetSymbolAddress((void**)&wkvb,   g_wkvb);
    cudaGetSymbolAddress((void**)&wo,     g_wo);
    cudaGetSymbolAddress((void**)&qa,     g_qa);
    cudaGetSymbolAddress((void**)&qn,     g_qn);
    cudaGetSymbolAddress((void**)&ckv,    g_ckv);
    cudaGetSymbolAddress((void**)&cnorm,  g_cnorm);
    cudaGetSymbolAddress((void**)&kpe,    g_kpe);
    cudaGetSymbolAddress((void**)&q,      g_q);
    cudaGetSymbolAddress((void**)&kv,     g_kv);
    cudaGetSymbolAddress((void**)&Q,      g_Q);
    cudaGetSymbolAddress((void**)&K,      g_K);
    cudaGetSymbolAddress((void**)&V,      g_V);
    cudaGetSymbolAddress((void**)&attn,   g_attn);

    cudaFuncSetAttribute(pgemm_kernel, cudaFuncAttributeMaxDynamicSharedMemorySize, SMEM_P);
    cudaFuncSetAttribute(flash_kernel, cudaFuncAttributeMaxDynamicSharedMemorySize, FLASH_SMEM);

    // prep: all conversions in 1 launch
    {
        int n0 = S_ * HID_ / 4, n1 = HID_ * QL_ / 4, n2 = QL_ * QDIM / 4,
            n3 = KVL_ * KVDIM / 4, n4 = H_ * D_V * HID_ / 4,
            n5 = HID_ * KVA_PAD / 4;
        int total = n0 + n1 + n2 + n3 + n4 + n5;
        conv_multi_kernel<<<(total + 255) / 256, 256>>>(
            (const float4*)x,      (__half2*)xc,   n0,
            (const float4*)q_a_w,  (__half2*)wqa,  n1,
            (const float4*)q_b_w,  (__half2*)wqb,  n2,
            (const float4*)kv_b_w, (__half2*)wkvb, n3,
            (const float4*)o_w,    (__half2*)wo,   n4,
            kv_a_w, wkva, n5);
    }

    dim3 blk5(512);

    // 1) fused: qa = x@q_a_w (6 tiles) ; ckv = x@kv_a_w (3 tiles, padded)
    pgemm_kernel<<<dim3(9, S_/128), blk5, SMEM_P>>>(
        xc, HID_, HID_, wqa, QL_, qa, QL_, QL_, 6,
        xc, HID_, HID_, wkva, KVA_PAD, ckv, CKV_W, CKV_W);
    // 2) fused RMSNorms
    rms_fused_kernel<<<dim3(S_, 2), 256>>>(qa, q_a_ln, ckv, kv_a_ln, cosT, sinT, pos,
                                           qn, cnorm, kpe, out_cache);
    // 3) fused: q = qn@q_b_w (12 tiles, K=1536) ; kv = cnorm@kv_b_w (16 tiles, K=512)
    pgemm_kernel<<<dim3(28, S_/128), blk5, SMEM_P>>>(
        qn, QL_, QL_, wqb, QDIM, q, QDIM, QDIM, 12,
        cnorm, KVL_, KVL_, wkvb, KVDIM, kv, KVDIM, KVDIM);
    // 4) fused assemble Q/K + V transpose
    assemble_fused_kernel<<<dim3(S_/64, H_), 256>>>(q, kv, kpe, cosT, sinT, pos, Q, K, V);
    // 5) fused flash attention (ascending qt — measured faster than heavy-first)
    flash_kernel<<<dim3(S_/64, H_), 256, FLASH_SMEM>>>(Q, K, V, attn);
    // 6) out = attn @ o_w
    pgemm_kernel<<<dim3(HID_/256, S_/128), blk5, SMEM_P>>>(
        attn, H_*D_V, H_*D_V, wo, HID_, out, HID_, HID_, HID_/256,
        nullptr, 0, 0, nullptr, 0, nullptr, 0, 0);
}

// round 12
// speedup vs baseline: 1.2988x; 1.2444x over previous
#include <cuda_runtime.h>
#include <cuda_fp16.h>
#include <mma.h>
#include <math.h>
#include <stdint.h>

using namespace nvcuda;

// ---------------- problem constants ----------------
#define S_      2048
#define HID_    2048
#define H_      16
#define D_NOPE  128
#define D_ROPE  64
#define D_V     128
#define QHEAD   192
#define QL_     1536
#define KVL_    512
#define CKV_W   576
#define KVA_PAD 768
#define QDIM    3072
#define KVDIM   4096
#define EPS_    1e-6f
#define SCALE_  0.07216878364870322f

// ---------------- scratch ----------------
__device__ __half g_x     [S_ * HID_];
__device__ __half g_wqa   [HID_ * QL_];
__device__ __half g_wqb   [QL_ * QDIM];
__device__ __half g_wkva  [HID_ * KVA_PAD];
__device__ __half g_wkvb  [KVL_ * KVDIM];
__device__ __half g_wo    [H_ * D_V * HID_];
__device__ float  g_qa    [S_ * QL_];
__device__ __half g_qn    [S_ * QL_];
__device__ float  g_ckv   [S_ * CKV_W];
__device__ __half g_cnorm [S_ * KVL_];
__device__ float  g_kpe   [S_ * D_ROPE];
__device__ float  g_q     [S_ * QDIM];
__device__ float  g_kv    [S_ * KVDIM];
__device__ __half g_Q     [H_ * S_ * QHEAD];
__device__ __half g_K     [H_ * S_ * QHEAD];
__device__ __half g_V     [H_ * D_V * S_];
__device__ __half g_attn  [S_ * (H_ * D_V)];

__device__ __forceinline__ int perm16(int c) {
    int j = c & 15;
    return (c & ~15) | (((j >> 1) & 3) << 2) | ((j >> 3) << 1) | (j & 1);
}
__device__ __forceinline__ uint32_t smem_u32(const void* p) {
    uint32_t a;
    asm("{ .reg .u64 t; cvta.to.shared.u64 t, %1; cvt.u32.u64 %0, t; }" : "=r"(a) : "l"(p));
    return a;
}
__device__ __forceinline__ void cp16(uint32_t d, const void* s) {
    asm volatile("cp.async.ca.shared.global [%0], [%1], 16;" :: "r"(d), "l"(s));
}
__device__ __forceinline__ void cp_commit() {
    asm volatile("cp.async.commit_group;" ::: "memory");
}
template<int N> __device__ __forceinline__ void cp_wait() {
    asm volatile("cp.async.wait_group %0;" :: "n"(N) : "memory");
}
__device__ __forceinline__ void mma16(float* c, uint32_t a0, uint32_t a1, uint32_t a2, uint32_t a3,
                                      uint32_t b0, uint32_t b1) {
    asm volatile(
        "mma.sync.aligned.m16n8k16.row.col.f32.f16.f16.f32 "
        "{%0,%1,%2,%3}, {%4,%5,%6,%7}, {%8,%9}, {%0,%1,%2,%3};"
        : "+f"(c[0]), "+f"(c[1]), "+f"(c[2]), "+f"(c[3])
        : "r"(a0), "r"(a1), "r"(a2), "r"(a3), "r"(b0), "r"(b1));
}
__device__ __forceinline__ uint32_t pack_h2(float lo, float hi) {
    __half2 p = __floats2half2_rn(lo, hi);
    return *reinterpret_cast<uint32_t*>(&p);
}

// ---------------- prep: fused fp16 conversion ----------------
__global__ void conv_multi_kernel(
    const float4* __restrict__ s0, __half2* __restrict__ d0, int n0,
    const float4* __restrict__ s1, __half2* __restrict__ d1, int n1,
    const float4* __restrict__ s2, __half2* __restrict__ d2, int n2,
    const float4* __restrict__ s3, __half2* __restrict__ d3, int n3,
    const float4* __restrict__ s4, __half2* __restrict__ d4, int n4,
    const float* __restrict__ kva, __half* __restrict__ wkva, int n5)
{
    int i = blockIdx.x * blockDim.x + threadIdx.x;
    int j = i;
    if (j < n0) {
        float4 v = s0[j];
        d0[2*j+0] = __floats2half2_rn(v.x, v.y); d0[2*j+1] = __floats2half2_rn(v.z, v.w);
        return;
    }
    j -= n0;
    if (j < n1) {
        float4 v = s1[j];
        d1[2*j+0] = __floats2half2_rn(v.x, v.y); d1[2*j+1] = __floats2half2_rn(v.z, v.w);
        return;
    }
    j -= n1;
    if (j < n2) {
        float4 v = s2[j];
        d2[2*j+0] = __floats2half2_rn(v.x, v.y); d2[2*j+1] = __floats2half2_rn(v.z, v.w);
        return;
    }
    j -= n2;
    if (j < n3) {
        float4 v = s3[j];
        d3[2*j+0] = __floats2half2_rn(v.x, v.y); d3[2*j+1] = __floats2half2_rn(v.z, v.w);
        return;
    }
    j -= n3;
    if (j < n4) {
        float4 v = s4[j];
        d4[2*j+0] = __floats2half2_rn(v.x, v.y); d4[2*j+1] = __floats2half2_rn(v.z, v.w);
        return;
    }
    j -= n4;
    if (j < n5) {
        int k = (4 * j) / KVA_PAD, n = (4 * j) % KVA_PAD;
        __half2 lo, hi;
        if (n < CKV_W) {
            float4 v = *reinterpret_cast<const float4*>(kva + (size_t)k * CKV_W + n);
            lo = __floats2half2_rn(v.x, v.y); hi = __floats2half2_rn(v.z, v.w);
        } else {
            lo = __floats2half2_rn(0.f, 0.f); hi = lo;
        }
        __half2* dp = reinterpret_cast<__half2*>(wkva + (size_t)k * KVA_PAD + n);
        dp[0] = lo; dp[1] = hi;
    }
}

// ---------------- pipelined fp16 GEMM, dual problem sets (round-8 config) ----------------
#define A_STRH 72
#define B_STRH 264
#define A_SBYT (128 * A_STRH * 2)
#define B_SBYT (64 * B_STRH * 2)
#define STG_P  (A_SBYT + B_SBYT)
#define SMEM_P (3 * STG_P)

__global__ __launch_bounds__(512, 1)
void pgemm_kernel(const __half* __restrict__ A, int lda, int K,
                  const __half* __restrict__ B, int ldb,
                  float* __restrict__ C, int ldc, int N, int nt1,
                  const __half* __restrict__ A2, int lda2, int K2,
                  const __half* __restrict__ B2, int ldb2,
                  float* __restrict__ C2, int ldc2, int N2)
{
    int bx = blockIdx.x;
    if (bx >= nt1) {
        A = A2; lda = lda2; K = K2; B = B2; ldb = ldb2; C = C2; ldc = ldc2; N = N2;
        bx -= nt1;
    }
    const int row0 = blockIdx.y * 128;
    const int col0 = bx * 256;
    const int nk = K / 64;

    extern __shared__ char smem[];
    const uint32_t sb = smem_u32(smem);
    const int tid = threadIdx.x;
    const int wid = tid >> 5;
    const int wm  = wid >> 3;
    const int wn  = wid & 7;

    auto issue = [&](int t) {
        const int s = t % 3;
        const int k0 = t * 64;
        uint32_t ab = sb + s * STG_P;
        #pragma unroll
        for (int i = 0; i < 2; i++) {
            int idx = i * 512 + tid;
            int r = idx >> 3, c = idx & 7;
            cp16(ab + r * (A_STRH * 2) + c * 16, A + (size_t)(row0 + r) * lda + k0 + c * 8);
        }
        uint32_t bb = sb + s * STG_P + A_SBYT;
        #pragma unroll
        for (int i = 0; i < 4; i++) {
            int idx = i * 512 + tid;
            int kr = idx >> 5, c = idx & 31;
            cp16(bb + kr * (B_STRH * 2) + c * 16, B + (size_t)(k0 + kr) * ldb + col0 + c * 8);
        }
    };

    typedef wmma::fragment<wmma::matrix_a, 16, 16, 16, __half, wmma::row_major> AFrag;
    typedef wmma::fragment<wmma::matrix_b, 16, 16, 16, __half, wmma::row_major> BFrag;
    wmma::fragment<wmma::accumulator, 16, 16, 16, float> acc[4][2];
    #pragma unroll
    for (int i = 0; i < 4; i++)
        #pragma unroll
        for (int j = 0; j < 2; j++) wmma::fill_fragment(acc[i][j], 0.0f);

    issue(0); cp_commit();
    if (nk > 1) { issue(1); cp_commit(); }

    for (int t = 0; t < nk; t++) {
        if (t + 1 < nk) cp_wait<1>(); else cp_wait<0>();
        __syncthreads();
        if (t + 2 < nk) { issue(t + 2); cp_commit(); }

        const __half* As = reinterpret_cast<const __half*>(smem + (t % 3) * STG_P);
        const __half* Bs = reinterpret_cast<const __half*>(smem + (t % 3) * STG_P + A_SBYT);

        #pragma unroll
        for (int kk = 0; kk < 4; kk++) {
            AFrag af[4];
            BFrag bf[2];
            #pragma unroll
            for (int mf = 0; mf < 4; mf++)
                wmma::load_matrix_sync(af[mf], As + (wm * 64 + mf * 16) * A_STRH + kk * 16, A_STRH);
            #pragma unroll
            for (int nf = 0; nf < 2; nf++)
                wmma::load_matrix_sync(bf[nf], Bs + (kk * 16) * B_STRH + wn * 32 + nf * 16, B_STRH);
            #pragma unroll
            for (int mf = 0; mf < 4; mf++)
                #pragma unroll
                for (int nf = 0; nf < 2; nf++)
                    wmma::mma_sync(acc[mf][nf], af[mf], bf[nf], acc[mf][nf]);
        }
    }

    #pragma unroll
    for (int mf = 0; mf < 4; mf++) {
        int gr = row0 + wm * 64 + mf * 16;
        #pragma unroll
        for (int nf = 0; nf < 2; nf++) {
            int gc = col0 + wn * 32 + nf * 16;
            if (gc + 16 <= N)
                wmma::store_matrix_sync(C + (size_t)gr * ldc + gc, acc[mf][nf], ldc,
                                        wmma::mem_row_major);
        }
    }
}

// ---------------- fused RMSNorm ----------------
__global__ __launch_bounds__(256)
void rms_fused_kernel(const float* __restrict__ qa, const float* __restrict__ wq,
                      const float* __restrict__ ckv, const float* __restrict__ wkv,
                      const float* __restrict__ cosT, const float* __restrict__ sinT,
                      const int* __restrict__ pos,
                      __half* __restrict__ qn, __half* __restrict__ cnorm,
                      float* __restrict__ kpe, float* __restrict__ cache)
{
    const int s = blockIdx.x;
    const int tid = threadIdx.x;
    __shared__ float sred[256];

    if (blockIdx.y == 0) {
        const float* x = qa + (size_t)s * QL_;
        __half*      y = qn + (size_t)s * QL_;
        float v[6];
        float local = 0.f;
        #pragma unroll
        for (int i = 0; i < 6; i++) { int c = tid + i * 256; v[i] = x[c]; local += v[i] * v[i]; }
        sred[tid] = local; __syncthreads();
        for (int st = 128; st > 0; st >>= 1) {
            if (tid < st) sred[tid] += sred[tid + st];
            __syncthreads();
        }
        float scale = rsqrtf(sred[0] / (float)QL_ + EPS_);
        #pragma unroll
        for (int i = 0; i < 6; i++) { int c = tid + i * 256; y[c] = __float2half(v[i] * scale * wq[c]); }
    } else {
        const float* x = ckv + (size_t)s * CKV_W;
        float v[2];
        float local = 0.f;
        #pragma unroll
        for (int i = 0; i < 2; i++) { int c = tid + i * 256; v[i] = x[c]; local += v[i] * v[i]; }
        sred[tid] = local; __syncthreads();
        for (int st = 128; st > 0; st >>= 1) {
            if (tid < st) sred[tid] += sred[tid + st];
            __syncthreads();
        }
        float scale = rsqrtf(sred[0] / (float)KVL_ + EPS_);
        #pragma unroll
        for (int i = 0; i < 2; i++) {
            int c = tid + i * 256;
            float y = v[i] * scale * wkv[c];
            cnorm[(size_t)s * KVL_ + c] = __float2half(y);
            cache[(size_t)s * CKV_W + c] = y;
        }
        if (tid < D_ROPE) {
            int p = pos[s];
            const float* cr = cosT + (size_t)p * D_ROPE;
            const float* sr = sinT + (size_t)p * D_ROPE;
            const float* t  = x + KVL_;
            int i = tid;
            float val;
            if (i < 32) val = t[2 * i] * cr[i] - t[2 * i + 1] * sr[i];
            else { int i2 = i - 32; val = t[2 * i2 + 1] * cr[i] + t[2 * i2] * sr[i]; }
            kpe[(size_t)s * D_ROPE + i] = val;
            cache[(size_t)s * CKV_W + KVL_ + i] = val;
        }
    }
}

// ---------------- fused assemble Q/K (perm16) + V transpose ----------------
__global__ __launch_bounds__(256)
void assemble_fused_kernel(const float* __restrict__ q, const float* __restrict__ kv,
                           const float* __restrict__ kpe,
                           const float* __restrict__ cosT, const float* __restrict__ sinT,
                           const int* __restrict__ pos,
                           __half* __restrict__ Q, __half* __restrict__ K,
                           __half* __restrict__ V)
{
    const int s0 = blockIdx.x * 64;
    const int h  = blockIdx.y;
    const int tid = threadIdx.x;

    #pragma unroll
    for (int it = 0; it < 48; it++) {
        int idx = it * 256 + tid;
        int sl = idx / QHEAD, d = idx % QHEAD;
        int s = s0 + sl;
        const float* qrow  = q  + (size_t)s * QDIM  + h * QHEAD;
        const float* kvrow = kv + (size_t)s * KVDIM + h * (D_NOPE + D_V);
        const size_t off = ((size_t)h * S_ + s) * QHEAD;

        float qv;
        if (d < D_NOPE) qv = qrow[d];
        else {
            int p = pos[s];
            const float* cr = cosT + (size_t)p * D_ROPE;
            const float* sr = sinT + (size_t)p * D_ROPE;
            const float* t  = qrow + D_NOPE;
            int i = d - D_NOPE;
            if (i < 32) qv = t[2 * i] * cr[i] - t[2 * i + 1] * sr[i];
            else { int i2 = i - 32; qv = t[2 * i2 + 1] * cr[i] + t[2 * i2] * sr[i]; }
        }
        float kvv = (d < D_NOPE) ? kvrow[d] : kpe[(size_t)s * D_ROPE + (d - D_NOPE)];
        int pd = perm16(d);
        Q[off + pd] = __float2half(qv);
        K[off + pd] = __float2half(kvv);
    }

    __shared__ float vt[64 * 132];
    #pragma unroll
    for (int i = 0; i < 32; i++) {
        int idx = i * 256 + tid;
        int sl = idx >> 7, d = idx & 127;
        vt[sl * 132 + d] = kv[(size_t)(s0 + sl) * KVDIM + h * (D_NOPE + D_V) + D_NOPE + d];
    }
    __syncthreads();
    #pragma unroll
    for (int i = 0; i < 32; i++) {
        int idx = i * 256 + tid;
        int d = idx >> 6, sl = idx & 63;
        V[((size_t)h * D_V + d) * S_ + s0 + perm16(sl)] = __float2half(vt[sl * 132 + d]);
    }
}

// ---------------- FA2 flash: in-register softmax, scores never touch smem ----------------
// 128 threads (4 warps x 16 rows = 64 q-rows), 32-key tiles double-buffered.
#define F2_QS_STR 200
#define F2_KS_STR 200
#define F2_VS_STR 40
#define F2_QS_OFF 0
#define F2_KS_OFF 25600            // 64*200*2
#define F2_KS_BYTES 12800          // 32*200*2
#define F2_VS_OFF (F2_KS_OFF + 2*F2_KS_BYTES)   // 51200
#define F2_VS_BYTES 10240          // 128*40*2
#define FLASH2_SMEM (F2_VS_OFF + 2*F2_VS_BYTES) // 71680

__global__ __launch_bounds__(128, 3)
void flash2_kernel(const __half* __restrict__ Q, const __half* __restrict__ K,
                   const __half* __restrict__ V, __half* __restrict__ attn)
{
    const int qt = blockIdx.x;
    const int h  = blockIdx.y;
    const int q0 = qt * 64;
    const int nt = 2 * qt + 2;

    extern __shared__ char sm[];
    const uint32_t sb = smem_u32(sm);

    const int tid = threadIdx.x;
    const int wid = tid >> 5;
    const int lid = tid & 31;
    const int gl  = lid >> 2;
    const int tg  = lid & 3;
    const int r0  = wid * 16 + gl;     // warp owns rows [wid*16, wid*16+16)

    const __half* Qg = Q + ((size_t)h * S_ + q0) * QHEAD;
    const __half* Kg = K + (size_t)h * S_ * QHEAD;
    const __half* Vg = V + (size_t)h * D_V * S_;

    auto issueKV = [&](int t, int st) {
        const __half* kp = Kg + (size_t)t * 32 * QHEAD;
        uint32_t kd = sb + F2_KS_OFF + st * F2_KS_BYTES;
        #pragma unroll
        for (int i = 0; i < 6; i++) {
            int idx = i * 128 + tid;
            int r = idx / 24, c = idx % 24;
            cp16(kd + r * (F2_KS_STR * 2) + c * 16, kp + (size_t)r * QHEAD + c * 8);
        }
        uint32_t vd = sb + F2_VS_OFF + st * F2_VS_BYTES;
        #pragma unroll
        for (int i = 0; i < 4; i++) {
            int idx = i * 128 + tid;
            int d = idx >> 2, c = idx & 3;
            cp16(vd + d * (F2_VS_STR * 2) + c * 16, Vg + (size_t)d * S_ + t * 32 + c * 8);
        }
    };

    // Q tile (resident) + KV tile 0
    #pragma unroll
    for (int i = 0; i < 12; i++) {
        int idx = i * 128 + tid;
        int r = idx / 24, c = idx % 24;
        cp16(sb + F2_QS_OFF + r * (F2_QS_STR * 2) + c * 16, Qg + (size_t)r * QHEAD + c * 8);
    }
    issueKV(0, 0);
    cp_commit();

    float m0 = -1e30f, m1 = -1e30f, l0 = 0.f, l1 = 0.f;
    float oacc[16][4];
    #pragma unroll
    for (int nf = 0; nf < 16; nf++)
        #pragma unroll
        for (int c = 0; c < 4; c++) oacc[nf][c] = 0.f;

    const char* QsB = sm + F2_QS_OFF;

    for (int t = 0; t < nt; t++) {
        const int st = t & 1;
        if (t + 1 < nt) { issueKV(t + 1, st ^ 1); cp_commit(); cp_wait<1>(); }
        else            { cp_wait<0>(); }
        __syncthreads();

        // ---- S = Q K^T : 16 rows x 32 keys per warp, fully in registers ----
        const char* KsB = sm + F2_KS_OFF + st * F2_KS_BYTES;
        float sacc[4][4];
        #pragma unroll
        for (int nf = 0; nf < 4; nf++)
            #pragma unroll
            for (int c = 0; c < 4; c++) sacc[nf][c] = 0.f;

        #pragma unroll 4
        for (int kk = 0; kk < 12; kk++) {
            uint2 qlo = *reinterpret_cast<const uint2*>(
                QsB + (r0 * F2_QS_STR + kk * 16 + 4 * tg) * 2);
            uint2 qhi = *reinterpret_cast<const uint2*>(
                QsB + ((r0 + 8) * F2_QS_STR + kk * 16 + 4 * tg) * 2);
            #pragma unroll
            for (int nf = 0; nf < 4; nf++) {
                uint2 bb = *reinterpret_cast<const uint2*>(
                    KsB + ((nf * 8 + gl) * F2_KS_STR + kk * 16 + 4 * tg) * 2);
                mma16(sacc[nf], qlo.x, qhi.x, qlo.y, qhi.y, bb.x, bb.y);
            }
        }

        // ---- in-register online softmax ----
        // sacc[nf][0,1]: row q0+r0,   keys t*32+nf*8+2tg, +1
        // sacc[nf][2,3]: row q0+r0+8, same keys
        const bool msk = (t >= 2 * qt);
        float mx0 = -1e30f, mx1 = -1e30f;
        #pragma unroll
        for (int nf = 0; nf < 4; nf++) {
            #pragma unroll
            for (int c = 0; c < 4; c++) {
                float val = sacc[nf][c] * SCALE_;
                if (msk) {
                    int key = t * 32 + nf * 8 + 2 * tg + (c & 1);
                    int row = q0 + r0 + ((c & 2) ? 8 : 0);
                    if (key > row) val = -1e30f;
                }
                sacc[nf][c] = val;
                if (c & 2) mx1 = fmaxf(mx1, val); else mx0 = fmaxf(mx0, val);
            }
        }
        mx0 = fmaxf(mx0, __shfl_xor_sync(0xffffffffu, mx0, 1));
        mx0 = fmaxf(mx0, __shfl_xor_sync(0xffffffffu, mx0, 2));
        mx1 = fmaxf(mx1, __shfl_xor_sync(0xffffffffu, mx1, 1));
        mx1 = fmaxf(mx1, __shfl_xor_sync(0xffffffffu, mx1, 2));

        float mn0 = fmaxf(m0, mx0), mn1 = fmaxf(m1, mx1);
        float al0 = __expf(m0 - mn0), al1 = __expf(m1 - mn1);
        m0 = mn0; m1 = mn1;

        float s0 = 0.f, s1 = 0.f;
        uint32_t pa[4][2];
        #pragma unroll
        for (int nf = 0; nf < 4; nf++) {
            float e0 = __expf(sacc[nf][0] - mn0);
            float e1 = __expf(sacc[nf][1] - mn0);
            float e2 = __expf(sacc[nf][2] - mn1);
            float e3 = __expf(sacc[nf][3] - mn1);
            s0 += e0 + e1; s1 += e2 + e3;
            pa[nf][0] = pack_h2(e0, e1);
            pa[nf][1] = pack_h2(e2, e3);
        }
        s0 += __shfl_xor_sync(0xffffffffu, s0, 1);
        s0 += __shfl_xor_sync(0xffffffffu, s0, 2);
        s1 += __shfl_xor_sync(0xffffffffu, s1, 1);
        s1 += __shfl_xor_sync(0xffffffffu, s1, 2);
        l0 = l0 * al0 + s0;
        l1 = l1 * al1 + s1;

        // ---- rescale O, then O += P V (P fed straight from registers) ----
        #pragma unroll
        for (int nf = 0; nf < 16; nf++) {
            oacc[nf][0] *= al0; oacc[nf][1] *= al0;
            oacc[nf][2] *= al1; oacc[nf][3] *= al1;
        }
        const char* VsB = sm + F2_VS_OFF + st * F2_VS_BYTES;
        #pragma unroll
        for (int kk2 = 0; kk2 < 2; kk2++) {
            uint32_t a0 = pa[2 * kk2][0];
            uint32_t a1 = pa[2 * kk2][1];
            uint32_t a2 = pa[2 * kk2 + 1][0];
            uint32_t a3 = pa[2 * kk2 + 1][1];
            #pragma unroll
            for (int nf = 0; nf < 16; nf++) {
                uint2 bv = *reinterpret_cast<const uint2*>(
                    VsB + ((nf * 8 + gl) * F2_VS_STR + kk2 * 16 + 4 * tg) * 2);
                mma16(oacc[nf], a0, a1, a2, a3, bv.x, bv.y);
            }
        }
        __syncthreads();   // all reads of buffer st done before its refill at t+2
    }

    // ---- epilogue: O / l ----
    float inv0 = 1.f / l0, inv1 = 1.f / l1;
    #pragma unroll
    for (int nf = 0; nf < 16; nf++) {
        int col = h * D_V + nf * 8 + 2 * tg;
        __half2* o0 = reinterpret_cast<__half2*>(attn + (size_t)(q0 + r0) * (H_ * D_V) + col);
        __half2* o8 = reinterpret_cast<__half2*>(attn + (size_t)(q0 + r0 + 8) * (H_ * D_V) + col);
        *o0 = __floats2half2_rn(oacc[nf][0] * inv0, oacc[nf][1] * inv0);
        *o8 = __floats2half2_rn(oacc[nf][2] * inv1, oacc[nf][3] * inv1);
    }
}

// ---------------- host launch ----------------
extern "C" void kernel_launch(void* const* d_in, const int* in_sizes, int n_in,
                              void* d_out, int out_size)
{
    const float* x       = (const float*)d_in[0];
    const int*   pos     = (const int*)  d_in[2];
    const float* cosT    = (const float*)d_in[3];
    const float* sinT    = (const float*)d_in[4];
    const float* q_a_w   = (const float*)d_in[5];
    const float* q_a_ln  = (const float*)d_in[6];
    const float* q_b_w   = (const float*)d_in[7];
    const float* kv_a_w  = (const float*)d_in[8];
    const float* kv_a_ln = (const float*)d_in[9];
    const float* kv_b_w  = (const float*)d_in[10];
    const float* o_w     = (const float*)d_in[11];
    float* out = (float*)d_out;
    float* out_cache = out + (size_t)S_ * HID_;

    __half *xc, *wqa, *wqb, *wkva, *wkvb, *wo, *qn, *cnorm, *Q, *K, *V, *attn;
    float *qa, *ckv, *kpe, *q, *kv;
    cudaGetSymbolAddress((void**)&xc,     g_x);
    cudaGetSymbolAddress((void**)&wqa,    g_wqa);
    cudaGetSymbolAddress((void**)&wqb,    g_wqb);
    cudaGetSymbolAddress((void**)&wkva,   g_wkva);
    cudaGetSymbolAddress((void**)&wkvb,   g_wkvb);
    cudaGetSymbolAddress((void**)&wo,     g_wo);
    cudaGetSymbolAddress((void**)&qa,     g_qa);
    cudaGetSymbolAddress((void**)&qn,     g_qn);
    cudaGetSymbolAddress((void**)&ckv,    g_ckv);
    cudaGetSymbolAddress((void**)&cnorm,  g_cnorm);
    cudaGetSymbolAddress((void**)&kpe,    g_kpe);
    cudaGetSymbolAddress((void**)&q,      g_q);
    cudaGetSymbolAddress((void**)&kv,     g_kv);
    cudaGetSymbolAddress((void**)&Q,      g_Q);
    cudaGetSymbolAddress((void**)&K,      g_K);
    cudaGetSymbolAddress((void**)&V,      g_V);
    cudaGetSymbolAddress((void**)&attn,   g_attn);

    cudaFuncSetAttribute(pgemm_kernel,  cudaFuncAttributeMaxDynamicSharedMemorySize, SMEM_P);
    cudaFuncSetAttribute(flash2_kernel, cudaFuncAttributeMaxDynamicSharedMemorySize, FLASH2_SMEM);

    // prep: all conversions in 1 launch
    {
        int n0 = S_ * HID_ / 4, n1 = HID_ * QL_ / 4, n2 = QL_ * QDIM / 4,
            n3 = KVL_ * KVDIM / 4, n4 = H_ * D_V * HID_ / 4,
            n5 = HID_ * KVA_PAD / 4;
        int total = n0 + n1 + n2 + n3 + n4 + n5;
        conv_multi_kernel<<<(total + 255) / 256, 256>>>(
            (const float4*)x,      (__half2*)xc,   n0,
            (const float4*)q_a_w,  (__half2*)wqa,  n1,
            (const float4*)q_b_w,  (__half2*)wqb,  n2,
            (const float4*)kv_b_w, (__half2*)wkvb, n3,
            (const float4*)o_w,    (__half2*)wo,   n4,
            kv_a_w, wkva, n5);
    }

    dim3 blk5(512);

    // 1) fused: qa = x@q_a_w ; ckv = x@kv_a_w (padded)
    pgemm_kernel<<<dim3(9, S_/128), blk5, SMEM_P>>>(
        xc, HID_, HID_, wqa, QL_, qa, QL_, QL_, 6,
        xc, HID_, HID_, wkva, KVA_PAD, ckv, CKV_W, CKV_W);
    // 2) fused RMSNorms
    rms_fused_kernel<<<dim3(S_, 2), 256>>>(qa, q_a_ln, ckv, kv_a_ln, cosT, sinT, pos,
                                           qn, cnorm, kpe, out_cache);
    // 3) fused: q = qn@q_b_w ; kv = cnorm@kv_b_w
    pgemm_kernel<<<dim3(28, S_/128), blk5, SMEM_P>>>(
        qn, QL_, QL_, wqb, QDIM, q, QDIM, QDIM, 12,
        cnorm, KVL_, KVL_, wkvb, KVDIM, kv, KVDIM, KVDIM);
    // 4) fused assemble Q/K + V transpose
    assemble_fused_kernel<<<dim3(S_/64, H_), 256>>>(q, kv, kpe, cosT, sinT, pos, Q, K, V);
    // 5) FA2 in-register flash attention
    flash2_kernel<<<dim3(S_/64, H_), 128, FLASH2_SMEM>>>(Q, K, V, attn);
    // 6) out = attn @ o_w
    pgemm_kernel<<<dim3(HID_/256, S_/128), blk5, SMEM_P>>>(
        attn, H_*D_V, H_*D_V, wo, HID_, out, HID_, HID_, HID_/256,
        nullptr, 0, 0, nullptr, 0, nullptr, 0, 0);
}